// round 12
// baseline (speedup 1.0000x reference)
#include <cuda_runtime.h>
#include <cstdint>

#define TOK 16384
#define LSEQ 4096
#define NB 4
#define DMO 64      // input/output dim D
#define DM 128      // d_model of mamba (2D)
#define DI 256      // d_inner
#define DS 16       // d_state
#define DTR 8       // dt_rank
#define NCH 1024    // NB * DI channels
#define CHK 64      // chunk length
#define NG (LSEQ / CHK)   // 64 chunks
#define NUNIT (NCH * NG)  // 65536 units

typedef unsigned long long ull;

__device__ __forceinline__ ull pk2(float a, float b) {
    ull r; asm("mov.b64 %0, {%1, %2};" : "=l"(r) : "f"(a), "f"(b)); return r;
}
__device__ __forceinline__ void fma2(ull& d, ull a, ull b) {
    asm("fma.rn.f32x2 %0, %1, %2, %3;" : "=l"(d) : "l"(a), "l"(b), "l"(d));
}
__device__ __forceinline__ float2 upk(ull v) {
    float2 r; asm("mov.b64 {%0, %1}, %2;" : "=f"(r.x), "=f"(r.y) : "l"(v)); return r;
}
__device__ __forceinline__ uint32_t tf32c(float f) {
    uint32_t r; asm("cvt.rna.tf32.f32 %0, %1;" : "=r"(r) : "f"(f)); return r;
}
__device__ __forceinline__ float tf32f(float f) {   // tf32-round, keep as float
    return __uint_as_float(tf32c(f));
}
// token permutation for vectorized B-fragment loads: t = nt*8+g stored at g*8+nt
__device__ __forceinline__ int permt(int t) { return ((t & 7) << 3) | (t >> 3); }

#define MMA_TF32(c, a0, a1, a2, a3, b0, b1) \
    asm volatile("mma.sync.aligned.m16n8k8.row.col.f32.tf32.tf32.f32 " \
        "{%0,%1,%2,%3}, {%4,%5,%6,%7}, {%8,%9}, {%0,%1,%2,%3};" \
        : "+f"((c)[0]), "+f"((c)[1]), "+f"((c)[2]), "+f"((c)[3]) \
        : "r"(a0), "r"(a1), "r"(a2), "r"(a3), "r"(b0), "r"(b1))

// 16 packed FMAs: 4 tokens-pairs x 4 outputs
#define FMA16(acc, x0, x1, x2, x3, wd0, wd1, wd2, wd3) \
    fma2(acc[0][0], x0, wd0); fma2(acc[0][1], x0, wd1); fma2(acc[0][2], x0, wd2); fma2(acc[0][3], x0, wd3); \
    fma2(acc[1][0], x1, wd0); fma2(acc[1][1], x1, wd1); fma2(acc[1][2], x1, wd2); fma2(acc[1][3], x1, wd3); \
    fma2(acc[2][0], x2, wd0); fma2(acc[2][1], x2, wd1); fma2(acc[2][2], x2, wd2); fma2(acc[2][3], x2, wd3); \
    fma2(acc[3][0], x3, wd0); fma2(acc[3][1], x3, wd1); fma2(acc[3][2], x3, wd2); fma2(acc[3][3], x3, wd3)

// ---------------- scratch ----------------
// xc / zs / delta / y are CHANNEL-MAJOR: [(b*DI + d) * LSEQ + l]
__device__ float g_Wu[DM * DMO];      // W_fp @ W_ip
__device__ float g_bu[DM];            // W_fp @ b_ip + b_fp
__device__ float g_Wc[2 * DI * DMO];  // in_proj @ W_u   (512 x 64)
__device__ float g_bc[2 * DI];        // in_proj @ b_u
__device__ float g_xn[TOK * DMO];
__device__ float g_u[TOK * DM];
__device__ float g_xc[NCH * LSEQ];
__device__ float g_zs[NCH * LSEQ];
__device__ float g_delta[NCH * LSEQ];
__device__ float g_Bm[TOK * DS];
__device__ float g_Cm[TOK * DS];
__device__ float g_y[NCH * LSEQ];
__device__ float g_m[TOK * DM];
__device__ float g_P[NUNIT * DS];
__device__ float g_q[NUNIT * DS];
__device__ float g_hin[NUNIT * DS];

// ---------------- K0: compose W_u = W_fp @ W_ip, b_u = W_fp@b_ip + b_fp ----------
__global__ void k_combine(const float* __restrict__ Wfp, const float* __restrict__ Wip,
                          const float* __restrict__ bip, const float* __restrict__ bfp) {
    int idx = blockIdx.x * 256 + threadIdx.x;
    int o = idx / DMO, i = idx % DMO;
    float s = 0.f;
    for (int k = 0; k < DM; ++k) s = fmaf(Wfp[o * DM + k], Wip[k * DMO + i], s);
    g_Wu[idx] = s;
    if (blockIdx.x == 0 && threadIdx.x < DM) {
        int t = threadIdx.x;
        float sb = bfp[t];
        for (int k = 0; k < DM; ++k) sb = fmaf(Wfp[t * DM + k], bip[k], sb);
        g_bu[t] = sb;
    }
}

// ---------------- K0b: compose W_c = in_proj @ W_u, b_c = in_proj @ b_u ----------
__global__ void k_combine2(const float* __restrict__ Win) {
    int idx = blockIdx.x * 256 + threadIdx.x;   // 128 blocks -> 32768 = 512*64
    int e = idx >> 6, i = idx & 63;
    float s = 0.f;
    for (int k = 0; k < DM; ++k) s = fmaf(Win[(long)e * DM + k], g_Wu[k * DMO + i], s);
    g_Wc[idx] = s;
    if (i == 0) {
        float sb = 0.f;
        for (int k = 0; k < DM; ++k) sb = fmaf(Win[(long)e * DM + k], g_bu[k], sb);
        g_bc[e] = sb;
    }
}

// ---------------- K1: rmsnorm1 + u = W_u @ xn + b_u ------------------------------
__global__ void __launch_bounds__(256, 3)
k_rms_u(const float* __restrict__ x, const float* __restrict__ wn1) {
    extern __shared__ float sm[];
    float* sx  = sm;                 // 64*68 [i][t]
    float* swT = sm + 64 * 68;       // 64*132 [i][o]  (+pad row for prefetch)
    float* ssc = swT + 65 * 132;     // 64
    int tid = threadIdx.x;
    long t0 = (long)blockIdx.x * 64;

    for (int idx = tid; idx < 64 * 64; idx += 256) {
        int i = idx & 63, t = idx >> 6;
        sx[i * 68 + t] = x[(t0 + t) * DMO + i];
    }
    for (int idx = tid; idx < DM * DMO; idx += 256) {
        int i = idx & 63, o = idx >> 6;
        swT[i * 132 + o] = g_Wu[o * DMO + i];
    }
    __syncthreads();
    if (tid < 64) {
        float ss = 0.f;
        for (int i = 0; i < DMO; ++i) { float v = sx[i * 68 + tid]; ss = fmaf(v, v, ss); }
        ssc[tid] = rsqrtf(ss * (1.f / DMO) + 1e-5f);
    }
    __syncthreads();
    for (int idx = tid; idx < 64 * 64; idx += 256) {
        int i = idx & 63, t = idx >> 6;
        float v = sx[i * 68 + t] * ssc[t] * wn1[i];
        sx[i * 68 + t] = v;
        g_xn[(t0 + t) * DMO + i] = v;
    }
    __syncthreads();
    int tx = tid & 31, ty = tid >> 5;
    ull acc[4][4] = {};
    float4 w4 = *(const float4*)&swT[tx << 2];
    ulonglong2 xa = *(const ulonglong2*)&sx[ty * 8];
    ulonglong2 xb = *(const ulonglong2*)&sx[ty * 8 + 4];
    #pragma unroll 8
    for (int i = 0; i < DMO; ++i) {
        ull wd0 = pk2(w4.x, w4.x), wd1 = pk2(w4.y, w4.y);
        ull wd2 = pk2(w4.z, w4.z), wd3 = pk2(w4.w, w4.w);
        ull x0 = xa.x, x1 = xa.y, x2 = xb.x, x3 = xb.y;
        w4 = *(const float4*)&swT[(i + 1) * 132 + (tx << 2)];
        xa = *(const ulonglong2*)&sx[(i + 1) * 68 + ty * 8];
        xb = *(const ulonglong2*)&sx[(i + 1) * 68 + ty * 8 + 4];
        FMA16(acc, x0, x1, x2, x3, wd0, wd1, wd2, wd3);
    }
    float4 bq = *(const float4*)&g_bu[tx << 2];
    #pragma unroll
    for (int p = 0; p < 4; ++p) {
        float2 v0 = upk(acc[p][0]), v1 = upk(acc[p][1]), v2 = upk(acc[p][2]), v3 = upk(acc[p][3]);
        long ta = t0 + ty * 8 + 2 * p, tb = ta + 1;
        float4 lo = make_float4(v0.x + bq.x, v1.x + bq.y, v2.x + bq.z, v3.x + bq.w);
        float4 hi = make_float4(v0.y + bq.x, v1.y + bq.y, v2.y + bq.z, v3.y + bq.w);
        *(float4*)&g_u[ta * DM + (tx << 2)] = lo;
        *(float4*)&g_u[tb * DM + (tx << 2)] = hi;
    }
}

// ---------------- K2: xz = W_c @ xn + b_c (tf32 MMA, permuted B layout) ----------
__global__ void __launch_bounds__(256, 3)
k_inproj(const float* __restrict__ cw, const float* __restrict__ cb) {
    extern __shared__ float sm[];
    float* sxn   = sm;                 // [i][permt(t)] 64*68 tf32 ; cols 64-66 halo
    float* swT   = sm + 64 * 68;       // [i][e] 64*132 tf32
    float* sbc   = sm + 12800 + 140;   // 128 biases (persists, fp32)
    float* stage = sm;                 // [e][t'] 128*68 AFTER GEMM (reuse)
    int tid = threadIdx.x;
    long t0 = (long)blockIdx.x * 64;
    int e0 = blockIdx.y * 128;
    int b = (int)(t0 >> 12);
    int l0 = (int)(t0 & (LSEQ - 1));
    bool isx = (e0 < DI);

    for (int idx = tid; idx < 64 * 64; idx += 256) {
        int i = idx & 63, t = idx >> 6;
        sxn[i * 68 + permt(t)] = tf32f(g_xn[(t0 + t) * DMO + i]);
    }
    for (int idx = tid; idx < 128 * 64; idx += 256) {
        int i = idx & 63, e = idx >> 6;
        swT[i * 132 + e] = tf32f(g_Wc[(long)(e0 + e) * DMO + i]);
    }
    if (tid < 128) sbc[tid] = g_bc[e0 + tid];
    if (isx && tid < 192) {   // halo xn: tokens t0-3..t0-1
        int i = tid & 63, j = tid >> 6;
        sxn[i * 68 + 64 + j] = (l0 > 0) ? tf32f(g_xn[(t0 - 3 + j) * DMO + i]) : 0.f;
    }
    __syncthreads();
    int warp = tid >> 5, lane = tid & 31, g = lane >> 2, tg = lane & 3;
    int ew = warp * 16;
    float c[8][4] = {};
    #pragma unroll
    for (int ks = 0; ks < 8; ++ks) {
        int kk = ks * 8;
        uint32_t a0 = __float_as_uint(swT[(kk + tg) * 132 + ew + g]);
        uint32_t a1 = __float_as_uint(swT[(kk + tg) * 132 + ew + g + 8]);
        uint32_t a2 = __float_as_uint(swT[(kk + tg + 4) * 132 + ew + g]);
        uint32_t a3 = __float_as_uint(swT[(kk + tg + 4) * 132 + ew + g + 8]);
        // vectorized B-fragments: 8 contiguous floats per k-row
        float4 q00 = *(const float4*)&sxn[(kk + tg) * 68 + g * 8];
        float4 q01 = *(const float4*)&sxn[(kk + tg) * 68 + g * 8 + 4];
        float4 q10 = *(const float4*)&sxn[(kk + tg + 4) * 68 + g * 8];
        float4 q11 = *(const float4*)&sxn[(kk + tg + 4) * 68 + g * 8 + 4];
        MMA_TF32(c[0], a0, a1, a2, a3, __float_as_uint(q00.x), __float_as_uint(q10.x));
        MMA_TF32(c[1], a0, a1, a2, a3, __float_as_uint(q00.y), __float_as_uint(q10.y));
        MMA_TF32(c[2], a0, a1, a2, a3, __float_as_uint(q00.z), __float_as_uint(q10.z));
        MMA_TF32(c[3], a0, a1, a2, a3, __float_as_uint(q00.w), __float_as_uint(q10.w));
        MMA_TF32(c[4], a0, a1, a2, a3, __float_as_uint(q01.x), __float_as_uint(q11.x));
        MMA_TF32(c[5], a0, a1, a2, a3, __float_as_uint(q01.y), __float_as_uint(q11.y));
        MMA_TF32(c[6], a0, a1, a2, a3, __float_as_uint(q01.z), __float_as_uint(q11.z));
        MMA_TF32(c[7], a0, a1, a2, a3, __float_as_uint(q01.w), __float_as_uint(q11.w));
    }
    // halo xz values -> registers (x blocks only); reads only halo cols 64-66
    float h1 = 0.f, h2 = 0.f;
    if (isx && l0 > 0) {
        {
            int j = tid >> 7, e = tid & 127;
            float a = sbc[e];
            for (int i = 0; i < 64; ++i)
                a = fmaf(sxn[i * 68 + 64 + j], swT[i * 132 + e], a);
            h1 = a;
        }
        if (tid < 128) {
            int e = tid;
            float a = sbc[e];
            for (int i = 0; i < 64; ++i)
                a = fmaf(sxn[i * 68 + 66], swT[i * 132 + e], a);
            h2 = a;
        }
    }
    __syncthreads();   // all reads of sxn/swT done -> reuse as stage
    {
        float bc0 = sbc[ew + g], bc1 = sbc[ew + g + 8];
        #pragma unroll
        for (int nt = 0; nt < 8; ++nt) {
            int t = nt * 8 + 2 * tg;
            stage[(ew + g) * 68 + 3 + t]     = c[nt][0] + bc0;
            stage[(ew + g) * 68 + 4 + t]     = c[nt][1] + bc0;
            stage[(ew + g + 8) * 68 + 3 + t] = c[nt][2] + bc1;
            stage[(ew + g + 8) * 68 + 4 + t] = c[nt][3] + bc1;
        }
    }
    if (isx) {
        { int j = tid >> 7, e = tid & 127; stage[e * 68 + j] = h1; }
        if (tid < 128) stage[tid * 68 + 2] = h2;
    }
    __syncthreads();
    if (isx) {
        for (int idx = tid; idx < 128 * 64; idx += 256) {
            int t = idx & 63, e = idx >> 6;
            int d = e0 + e;
            const float* st = &stage[e * 68];
            float4 w = *(const float4*)&cw[d * 4];
            float a = cb[d];
            a = fmaf(w.x, st[t], a);
            a = fmaf(w.y, st[t + 1], a);
            a = fmaf(w.z, st[t + 2], a);
            a = fmaf(w.w, st[t + 3], a);
            a = a / (1.f + __expf(-a));
            g_xc[(long)(b * DI + d) * LSEQ + l0 + t] = a;
        }
    } else {
        for (int idx = tid; idx < 128 * 64; idx += 256) {
            int t = idx & 63, e = idx >> 6;
            float v = stage[e * 68 + 3 + t];
            v = v / (1.f + __expf(-v));
            g_zs[(long)(b * DI + (e0 - DI) + e) * LSEQ + l0 + t] = v;
        }
    }
}

// ---------------- K4: x_dbl = x_proj @ x ; B,C ; delta (K-chunked, smem reuse) ---
__global__ void __launch_bounds__(256, 2)
k_xproj(const float* __restrict__ Xp, const float* __restrict__ Wdt,
        const float* __restrict__ bdt) {
    extern __shared__ float sm[];
    float* sdbl = sm;                 // 64*40 (persists)
    float* sxc  = sm + 2560;          // phase1: [t][kk] 64*132
    float* spc  = sm + 2560 + 8448;   // phase1: [e][kk] 40*132
    float* sdel = sm + 2560;          // phase2: [d][t] 256*65 (reuses chunk region)
    int tid = threadIdx.x;
    long t0 = (long)blockIdx.x * 64;
    int b = (int)(t0 >> 12);
    int l0 = (int)(t0 & (LSEQ - 1));

    int tt = tid >> 2, eb = (tid & 3) * 10;
    float acc[10] = {};
    for (int kc = 0; kc < 2; ++kc) {
        __syncthreads();
        for (int idx = tid; idx < 64 * 128; idx += 256) {
            int t = idx & 63, kk = idx >> 6;
            sxc[t * 132 + kk] = g_xc[(long)(b * DI + kc * 128 + kk) * LSEQ + l0 + t];
        }
        for (int idx = tid; idx < 40 * 128; idx += 256) {
            int kk = idx & 127, e = idx >> 7;
            spc[e * 132 + kk] = Xp[e * DI + kc * 128 + kk];
        }
        __syncthreads();
        for (int kk = 0; kk < 128; kk += 4) {
            float4 xv = *(const float4*)&sxc[tt * 132 + kk];
            #pragma unroll
            for (int e = 0; e < 10; ++e) {
                float4 wv = *(const float4*)&spc[(eb + e) * 132 + kk];
                acc[e] = fmaf(xv.x, wv.x, fmaf(xv.y, wv.y, fmaf(xv.z, wv.z, fmaf(xv.w, wv.w, acc[e]))));
            }
        }
    }
    __syncthreads();
    #pragma unroll
    for (int e = 0; e < 10; ++e) sdbl[tt * 40 + eb + e] = acc[e];
    __syncthreads();
    for (int idx = tid; idx < 64 * DS; idx += 256) {
        int t = idx >> 4, s = idx & 15;
        g_Bm[(t0 + t) * DS + s] = sdbl[t * 40 + 8 + s];
        g_Cm[(t0 + t) * DS + s] = sdbl[t * 40 + 24 + s];
    }
    {
        int d = tid;
        float wr[8];
        #pragma unroll
        for (int r = 0; r < 8; ++r) wr[r] = Wdt[d * 8 + r];
        float bb = bdt[d];
        for (int t = 0; t < 64; ++t) {
            float pre = bb;
            #pragma unroll
            for (int r = 0; r < 8; ++r) pre = fmaf(sdbl[t * 40 + r], wr[r], pre);
            float sp = (pre > 20.f) ? pre : log1pf(__expf(pre));
            sdel[d * 65 + t] = sp;
        }
    }
    __syncthreads();
    for (int idx = tid; idx < DI * 64; idx += 256) {
        int d = idx >> 6, t = idx & 63;
        g_delta[(long)(b * DI + d) * LSEQ + l0 + t] = sdel[d * 65 + t];
    }
}

// ---------------- K5a: per-chunk decay product P and local state q ----------------
__global__ void __launch_bounds__(256, 6)
k_scan1(const float* __restrict__ Alog) {
    int u = threadIdx.x >> 4;
    int s = threadIdx.x & 15;
    int unit = blockIdx.x * 16 + u;
    int g = unit & (NG - 1);
    int ch = unit >> 6;
    int b = ch >> 8, d = ch & 255;
    float Aval = -__expf(Alog[d * DS + s]);
    const float* pd = g_delta + (long)ch * LSEQ + g * CHK;
    const float* px = g_xc    + (long)ch * LSEQ + g * CHK;
    const float* pB = g_Bm    + ((long)b * LSEQ + g * CHK) * DS + s;
    float P = 1.f, q = 0.f;
    #pragma unroll 4
    for (int t = 0; t < CHK; t += 4) {
        float4 dv = *(const float4*)&pd[t];
        float4 xv = *(const float4*)&px[t];
        float B0 = pB[(t + 0) * DS], B1 = pB[(t + 1) * DS];
        float B2 = pB[(t + 2) * DS], B3 = pB[(t + 3) * DS];
        float a0 = __expf(dv.x * Aval); P *= a0; q = fmaf(a0, q, dv.x * xv.x * B0);
        float a1 = __expf(dv.y * Aval); P *= a1; q = fmaf(a1, q, dv.y * xv.y * B1);
        float a2 = __expf(dv.z * Aval); P *= a2; q = fmaf(a2, q, dv.z * xv.z * B2);
        float a3 = __expf(dv.w * Aval); P *= a3; q = fmaf(a3, q, dv.w * xv.w * B3);
    }
    long idx = (long)unit * DS + s;
    g_P[idx] = P;
    g_q[idx] = q;
}

// ---------------- K5b: propagate h_in across chunks ------------------------------
__global__ void k_scan2() {
    int tid = blockIdx.x * 256 + threadIdx.x;
    int ch = tid >> 4, s = tid & 15;
    float h = 0.f;
    long base = (long)ch * NG * DS + s;
    #pragma unroll 8
    for (int g = 0; g < NG; ++g) {
        long idx = base + (long)g * DS;
        g_hin[idx] = h;
        h = fmaf(g_P[idx], h, g_q[idx]);
    }
}

// ---------------- K5c: local scan from h_in, y = (C.h + x*D) * silu(z) -----------
__global__ void __launch_bounds__(256, 6)
k_scan3(const float* __restrict__ Alog, const float* __restrict__ Dp_) {
    __shared__ float ybuf[16 * CHK];
    int u = threadIdx.x >> 4;
    int s = threadIdx.x & 15;
    int unit = blockIdx.x * 16 + u;
    int g = unit & (NG - 1);
    int ch = unit >> 6;
    int b = ch >> 8, d = ch & 255;
    float Aval = -__expf(Alog[d * DS + s]);
    float Dp = Dp_[d];
    const float* pd = g_delta + (long)ch * LSEQ + g * CHK;
    const float* px = g_xc    + (long)ch * LSEQ + g * CHK;
    const float* pz = g_zs    + (long)ch * LSEQ + g * CHK;
    const float* pB = g_Bm    + ((long)b * LSEQ + g * CHK) * DS + s;
    const float* pC = g_Cm    + ((long)b * LSEQ + g * CHK) * DS + s;
    float h = g_hin[(long)unit * DS + s];
    #pragma unroll 2
    for (int t = 0; t < CHK; t += 4) {
        float4 dv = *(const float4*)&pd[t];
        float4 xv = *(const float4*)&px[t];
        float4 zv;
        if (s == 0) zv = *(const float4*)&pz[t];
        #pragma unroll
        for (int j = 0; j < 4; ++j) {
            float dvj = (j == 0) ? dv.x : (j == 1) ? dv.y : (j == 2) ? dv.z : dv.w;
            float xvj = (j == 0) ? xv.x : (j == 1) ? xv.y : (j == 2) ? xv.z : xv.w;
            float Bv = pB[(t + j) * DS];
            float Cv = pC[(t + j) * DS];
            float a = __expf(dvj * Aval);
            h = fmaf(a, h, dvj * xvj * Bv);
            float p = h * Cv;
            p += __shfl_xor_sync(0xffffffffu, p, 8);
            p += __shfl_xor_sync(0xffffffffu, p, 4);
            p += __shfl_xor_sync(0xffffffffu, p, 2);
            p += __shfl_xor_sync(0xffffffffu, p, 1);
            if (s == 0) {
                float zvj = (j == 0) ? zv.x : (j == 1) ? zv.y : (j == 2) ? zv.z : zv.w;
                ybuf[u * CHK + t + j] = (p + xvj * Dp) * zvj;
            }
        }
    }
    __syncthreads();
    float* py = g_y + (long)ch * LSEQ + (long)(blockIdx.x & 3) * 1024;
    for (int i = threadIdx.x; i < 16 * CHK; i += 256) py[i] = ybuf[i];
}

// ---------------- K6: m = rmsnorm2(mamba_out @ y) + u (tf32 MMA, permuted B) -----
__global__ void __launch_bounds__(256, 3)
k_outproj(const float* __restrict__ Wmo, const float* __restrict__ wn2) {
    extern __shared__ float sm[];
    float* syT = sm;               // [k][permt(t)] 64*68 chunk (tf32)
    float* swT = sm + 64 * 68;     // [k][o] 64*132 chunk (tf32) ; later stage [t][o]
    int tid = threadIdx.x;
    long t0 = (long)blockIdx.x * 64;
    int b = (int)(t0 >> 12);
    int lpos = (int)(t0 & (LSEQ - 1));
    int warp = tid >> 5, lane = tid & 31, g = lane >> 2, tg = lane & 3;
    int o0 = warp * 16;

    float c[8][4] = {};
    for (int kc = 0; kc < 4; ++kc) {
        __syncthreads();
        for (int idx = tid; idx < 64 * 16; idx += 256) {
            int t4 = idx & 15, k = idx >> 4;
            float4 v = *(const float4*)&g_y[(long)(b * DI + kc * 64 + k) * LSEQ + lpos + t4 * 4];
            int tb = t4 * 4;
            syT[k * 68 + permt(tb + 0)] = tf32f(v.x);
            syT[k * 68 + permt(tb + 1)] = tf32f(v.y);
            syT[k * 68 + permt(tb + 2)] = tf32f(v.z);
            syT[k * 68 + permt(tb + 3)] = tf32f(v.w);
        }
        for (int idx = tid; idx < 64 * DM; idx += 256) {
            int k = idx & 63, o = idx >> 6;
            swT[k * 132 + o] = tf32f(Wmo[(long)o * DI + kc * 64 + k]);
        }
        __syncthreads();
        #pragma unroll
        for (int ks = 0; ks < 8; ++ks) {
            int kk = ks * 8;
            uint32_t a0 = __float_as_uint(swT[(kk + tg) * 132 + o0 + g]);
            uint32_t a1 = __float_as_uint(swT[(kk + tg) * 132 + o0 + g + 8]);
            uint32_t a2 = __float_as_uint(swT[(kk + tg + 4) * 132 + o0 + g]);
            uint32_t a3 = __float_as_uint(swT[(kk + tg + 4) * 132 + o0 + g + 8]);
            float4 q00 = *(const float4*)&syT[(kk + tg) * 68 + g * 8];
            float4 q01 = *(const float4*)&syT[(kk + tg) * 68 + g * 8 + 4];
            float4 q10 = *(const float4*)&syT[(kk + tg + 4) * 68 + g * 8];
            float4 q11 = *(const float4*)&syT[(kk + tg + 4) * 68 + g * 8 + 4];
            MMA_TF32(c[0], a0, a1, a2, a3, __float_as_uint(q00.x), __float_as_uint(q10.x));
            MMA_TF32(c[1], a0, a1, a2, a3, __float_as_uint(q00.y), __float_as_uint(q10.y));
            MMA_TF32(c[2], a0, a1, a2, a3, __float_as_uint(q00.z), __float_as_uint(q10.z));
            MMA_TF32(c[3], a0, a1, a2, a3, __float_as_uint(q00.w), __float_as_uint(q10.w));
            MMA_TF32(c[4], a0, a1, a2, a3, __float_as_uint(q01.x), __float_as_uint(q11.x));
            MMA_TF32(c[5], a0, a1, a2, a3, __float_as_uint(q01.y), __float_as_uint(q11.y));
            MMA_TF32(c[6], a0, a1, a2, a3, __float_as_uint(q01.z), __float_as_uint(q11.z));
            MMA_TF32(c[7], a0, a1, a2, a3, __float_as_uint(q01.w), __float_as_uint(q11.w));
        }
    }
    __syncthreads();   // swT reads done -> reuse as [t][o] stage
    float* stage = swT;
    #pragma unroll
    for (int nt = 0; nt < 8; ++nt) {
        int t = nt * 8 + 2 * tg;
        stage[t * 132 + o0 + g]           = c[nt][0];
        stage[(t + 1) * 132 + o0 + g]     = c[nt][1];
        stage[t * 132 + o0 + g + 8]       = c[nt][2];
        stage[(t + 1) * 132 + o0 + g + 8] = c[nt][3];
    }
    __syncthreads();
    {
        int t = tid >> 2, part = tid & 3;
        int ob = part * 32;
        float ss = 0.f;
        #pragma unroll
        for (int j = 0; j < 32; j += 4) {
            float4 v = *(const float4*)&stage[t * 132 + ob + j];
            ss = fmaf(v.x, v.x, fmaf(v.y, v.y, fmaf(v.z, v.z, fmaf(v.w, v.w, ss))));
        }
        ss += __shfl_xor_sync(0xffffffffu, ss, 1);
        ss += __shfl_xor_sync(0xffffffffu, ss, 2);
        float sc = rsqrtf(ss * (1.f / DM) + 1e-5f);
        long tt = t0 + t;
        #pragma unroll
        for (int j = 0; j < 32; j += 4) {
            float4 v  = *(const float4*)&stage[t * 132 + ob + j];
            float4 w2 = *(const float4*)&wn2[ob + j];
            float4 uq = *(const float4*)&g_u[tt * DM + ob + j];
            float4 ov = make_float4(v.x * sc * w2.x + uq.x, v.y * sc * w2.y + uq.y,
                                    v.z * sc * w2.z + uq.z, v.w * sc * w2.w + uq.w);
            *(float4*)&g_m[tt * DM + ob + j] = ov;
        }
    }
}

// ---------------- K7: w = swish(W_wp@xn+b) ; out = W_op@(w*m)+b + x ---------------
__global__ void __launch_bounds__(256, 2)
k_final(const float* __restrict__ Wwp, const float* __restrict__ bwp,
        const float* __restrict__ Wop, const float* __restrict__ bop,
        const float* __restrict__ x, float* __restrict__ out) {
    extern __shared__ float sm[];
    float* smm  = sm;                      // [t][c] 64*132 (persists)
    float* sxn  = sm + 64 * 132;           // [i][t] 64*68 (phase 1)
    float* swpT = sm + 64 * 132 + 64 * 68; // [i][c] 64*132 (phase 1, +pad)
    float* sopT = sm + 64 * 132;           // [c][o] 128*68 (phase 2, reuse)
    int tid = threadIdx.x;
    long t0 = (long)blockIdx.x * 64;

    for (int idx = tid; idx < 64 * DM; idx += 256) {
        int c = idx & 127, t = idx >> 7;
        smm[t * 132 + c] = g_m[(t0 + t) * DM + c];
    }
    for (int idx = tid; idx < 64 * 64; idx += 256) {
        int i = idx & 63, t = idx >> 6;
        sxn[i * 68 + t] = g_xn[(t0 + t) * DMO + i];
    }
    for (int idx = tid; idx < DM * DMO; idx += 256) {
        int i = idx & 63, c = idx >> 6;
        swpT[i * 132 + c] = Wwp[c * DMO + i];
    }
    __syncthreads();
    int tx = tid & 31, ty = tid >> 5;
    {
        ull acc[4][4] = {};
        float4 w4 = *(const float4*)&swpT[tx << 2];
        ulonglong2 xa = *(const ulonglong2*)&sxn[ty * 8];
        ulonglong2 xb = *(const ulonglong2*)&sxn[ty * 8 + 4];
        #pragma unroll 8
        for (int i = 0; i < DMO; ++i) {
            ull wd0 = pk2(w4.x, w4.x), wd1 = pk2(w4.y, w4.y);
            ull wd2 = pk2(w4.z, w4.z), wd3 = pk2(w4.w, w4.w);
            ull x0 = xa.x, x1 = xa.y, x2 = xb.x, x3 = xb.y;
            w4 = *(const float4*)&swpT[(i + 1) * 132 + (tx << 2)];
            xa = *(const ulonglong2*)&sxn[(i + 1) * 68 + ty * 8];
            xb = *(const ulonglong2*)&sxn[(i + 1) * 68 + ty * 8 + 4];
            FMA16(acc, x0, x1, x2, x3, wd0, wd1, wd2, wd3);
        }
        float4 bq = *(const float4*)&bwp[tx << 2];
        float bj[4] = {bq.x, bq.y, bq.z, bq.w};
        #pragma unroll
        for (int p = 0; p < 4; ++p)
            #pragma unroll
            for (int j = 0; j < 4; ++j) {
                float2 v = upk(acc[p][j]);
                int c = (tx << 2) + j;
                int ta = ty * 8 + 2 * p;
                float va = v.x + bj[j], vb = v.y + bj[j];
                float wa = va / (1.f + __expf(-va));
                float wb = vb / (1.f + __expf(-vb));
                smm[ta * 132 + c] *= wa;
                smm[(ta + 1) * 132 + c] *= wb;
            }
    }
    __syncthreads();   // sxn/swpT dead -> load sopT
    for (int idx = tid; idx < DMO * DM; idx += 256) {
        int c = idx & 127, o = idx >> 7;
        sopT[c * 68 + o] = Wop[o * DM + c];
    }
    __syncthreads();
    {
        int rowg = tid >> 4;
        int o4 = (tid & 15) << 2;
        float a2[4][4] = {};
        for (int c = 0; c < DM; c += 4) {
            float4 q0 = *(const float4*)&sopT[(c + 0) * 68 + o4];
            float4 q1 = *(const float4*)&sopT[(c + 1) * 68 + o4];
            float4 q2 = *(const float4*)&sopT[(c + 2) * 68 + o4];
            float4 q3 = *(const float4*)&sopT[(c + 3) * 68 + o4];
            #pragma unroll
            for (int rr = 0; rr < 4; ++rr) {
                float4 pv = *(const float4*)&smm[(rowg * 4 + rr) * 132 + c];
                a2[rr][0] = fmaf(pv.x, q0.x, fmaf(pv.y, q1.x, fmaf(pv.z, q2.x, fmaf(pv.w, q3.x, a2[rr][0]))));
                a2[rr][1] = fmaf(pv.x, q0.y, fmaf(pv.y, q1.y, fmaf(pv.z, q2.y, fmaf(pv.w, q3.y, a2[rr][1]))));
                a2[rr][2] = fmaf(pv.x, q0.z, fmaf(pv.y, q1.z, fmaf(pv.z, q2.z, fmaf(pv.w, q3.z, a2[rr][2]))));
                a2[rr][3] = fmaf(pv.x, q0.w, fmaf(pv.y, q1.w, fmaf(pv.z, q2.w, fmaf(pv.w, q3.w, a2[rr][3]))));
            }
        }
        float4 bq = *(const float4*)&bop[o4];
        #pragma unroll
        for (int rr = 0; rr < 4; ++rr) {
            long tg = t0 + rowg * 4 + rr;
            float4 xq = *(const float4*)&x[tg * DMO + o4];
            float4 ov = make_float4(a2[rr][0] + bq.x + xq.x, a2[rr][1] + bq.y + xq.y,
                                    a2[rr][2] + bq.z + xq.z, a2[rr][3] + bq.w + xq.w);
            *(float4*)&out[tg * DMO + o4] = ov;
        }
    }
}

// ---------------- launch -----------------------------------------------------------
extern "C" void kernel_launch(void* const* d_in, const int* in_sizes, int n_in,
                              void* d_out, int out_size) {
    const float* x    = (const float*)d_in[0];
    const float* wn1  = (const float*)d_in[1];
    const float* wn2  = (const float*)d_in[2];
    const float* Wip  = (const float*)d_in[3];
    const float* bip  = (const float*)d_in[4];
    const float* Wfp  = (const float*)d_in[5];
    const float* bfp  = (const float*)d_in[6];
    const float* Wwp  = (const float*)d_in[7];
    const float* bwp  = (const float*)d_in[8];
    const float* Wop  = (const float*)d_in[9];
    const float* bop  = (const float*)d_in[10];
    const float* Win  = (const float*)d_in[11];
    const float* cw   = (const float*)d_in[12];
    const float* cb   = (const float*)d_in[13];
    const float* Xp   = (const float*)d_in[14];
    const float* Wdt  = (const float*)d_in[15];
    const float* bdt  = (const float*)d_in[16];
    const float* Alog = (const float*)d_in[17];
    const float* Dpar = (const float*)d_in[18];
    const float* Wmo  = (const float*)d_in[19];
    float* out = (float*)d_out;

    const int SM_K1 = (64 * 68 + 65 * 132 + 64 + 16) * 4;
    const int SM_K2 = (12800 + 140 + 128 + 16) * 4;
    const int SM_K4 = (2560 + 256 * 65) * 4;
    const int SM_K6 = (64 * 68 + 64 * 132) * 4;
    const int SM_K7 = (64 * 132 + 64 * 68 + 65 * 132 + 16) * 4;

    cudaFuncSetAttribute(k_rms_u,   cudaFuncAttributeMaxDynamicSharedMemorySize, SM_K1);
    cudaFuncSetAttribute(k_inproj,  cudaFuncAttributeMaxDynamicSharedMemorySize, SM_K2);
    cudaFuncSetAttribute(k_xproj,   cudaFuncAttributeMaxDynamicSharedMemorySize, SM_K4);
    cudaFuncSetAttribute(k_outproj, cudaFuncAttributeMaxDynamicSharedMemorySize, SM_K6);
    cudaFuncSetAttribute(k_final,   cudaFuncAttributeMaxDynamicSharedMemorySize, SM_K7);

    k_combine<<<32, 256>>>(Wfp, Wip, bip, bfp);
    k_combine2<<<128, 256>>>(Win);
    k_rms_u<<<TOK / 64, 256, SM_K1>>>(x, wn1);
    k_inproj<<<dim3(TOK / 64, 4), 256, SM_K2>>>(cw, cb);
    k_xproj<<<TOK / 64, 256, SM_K4>>>(Xp, Wdt, bdt);
    k_scan1<<<NUNIT / 16, 256>>>(Alog);
    k_scan2<<<64, 256>>>();
    k_scan3<<<NUNIT / 16, 256>>>(Alog, Dpar);
    k_outproj<<<TOK / 64, 256, SM_K6>>>(Wmo, wn2);
    k_final<<<TOK / 64, 256, SM_K7>>>(Wwp, bwp, Wop, bop, x, out);
}

// round 13
// speedup vs baseline: 1.0356x; 1.0356x over previous
#include <cuda_runtime.h>
#include <cstdint>

#define TOK 16384
#define LSEQ 4096
#define NB 4
#define DMO 64      // input/output dim D
#define DM 128      // d_model of mamba (2D)
#define DI 256      // d_inner
#define DS 16       // d_state
#define DTR 8       // dt_rank
#define NCH 1024    // NB * DI channels
#define CHK 64      // chunk length
#define NG (LSEQ / CHK)   // 64 chunks
#define NUNIT (NCH * NG)  // 65536 units

typedef unsigned long long ull;

__device__ __forceinline__ ull pk2(float a, float b) {
    ull r; asm("mov.b64 %0, {%1, %2};" : "=l"(r) : "f"(a), "f"(b)); return r;
}
__device__ __forceinline__ void fma2(ull& d, ull a, ull b) {
    asm("fma.rn.f32x2 %0, %1, %2, %3;" : "=l"(d) : "l"(a), "l"(b), "l"(d));
}
__device__ __forceinline__ float2 upk(ull v) {
    float2 r; asm("mov.b64 {%0, %1}, %2;" : "=f"(r.x), "=f"(r.y) : "l"(v)); return r;
}
__device__ __forceinline__ uint32_t tf32c(float f) {
    uint32_t r; asm("cvt.rna.tf32.f32 %0, %1;" : "=r"(r) : "f"(f)); return r;
}
__device__ __forceinline__ float tf32f(float f) {   // tf32-round, keep as float
    return __uint_as_float(tf32c(f));
}
// token permutation for vectorized B-fragment loads: t = nt*8+g stored at g*8+nt
__device__ __forceinline__ int permt(int t) { return ((t & 7) << 3) | (t >> 3); }

#define MMA_TF32(c, a0, a1, a2, a3, b0, b1) \
    asm volatile("mma.sync.aligned.m16n8k8.row.col.f32.tf32.tf32.f32 " \
        "{%0,%1,%2,%3}, {%4,%5,%6,%7}, {%8,%9}, {%0,%1,%2,%3};" \
        : "+f"((c)[0]), "+f"((c)[1]), "+f"((c)[2]), "+f"((c)[3]) \
        : "r"(a0), "r"(a1), "r"(a2), "r"(a3), "r"(b0), "r"(b1))

// 16 packed FMAs: 4 tokens-pairs x 4 outputs
#define FMA16(acc, x0, x1, x2, x3, wd0, wd1, wd2, wd3) \
    fma2(acc[0][0], x0, wd0); fma2(acc[0][1], x0, wd1); fma2(acc[0][2], x0, wd2); fma2(acc[0][3], x0, wd3); \
    fma2(acc[1][0], x1, wd0); fma2(acc[1][1], x1, wd1); fma2(acc[1][2], x1, wd2); fma2(acc[1][3], x1, wd3); \
    fma2(acc[2][0], x2, wd0); fma2(acc[2][1], x2, wd1); fma2(acc[2][2], x2, wd2); fma2(acc[2][3], x2, wd3); \
    fma2(acc[3][0], x3, wd0); fma2(acc[3][1], x3, wd1); fma2(acc[3][2], x3, wd2); fma2(acc[3][3], x3, wd3)

// ---------------- scratch ----------------
// xc / zs / delta / y are CHANNEL-MAJOR: [(b*DI + d) * LSEQ + l]
__device__ float g_Wu[DM * DMO];      // W_fp @ W_ip
__device__ float g_bu[DM];            // W_fp @ b_ip + b_fp
__device__ float g_Wc[2 * DI * DMO];  // in_proj @ W_u   (512 x 64)
__device__ float g_bc[2 * DI];        // in_proj @ b_u
__device__ float g_xn[TOK * DMO];
__device__ float g_u[TOK * DM];
__device__ float g_xc[NCH * LSEQ];
__device__ float g_zs[NCH * LSEQ];
__device__ float g_delta[NCH * LSEQ];
__device__ float g_Bm[TOK * DS];
__device__ float g_Cm[TOK * DS];
__device__ float g_y[NCH * LSEQ];
__device__ float g_P[NUNIT * DS];
__device__ float g_q[NUNIT * DS];
__device__ float g_hin[NUNIT * DS];

// ---------------- K0: compose W_u = W_fp @ W_ip, b_u = W_fp@b_ip + b_fp ----------
__global__ void k_combine(const float* __restrict__ Wfp, const float* __restrict__ Wip,
                          const float* __restrict__ bip, const float* __restrict__ bfp) {
    int idx = blockIdx.x * 256 + threadIdx.x;
    int o = idx / DMO, i = idx % DMO;
    float s = 0.f;
    for (int k = 0; k < DM; ++k) s = fmaf(Wfp[o * DM + k], Wip[k * DMO + i], s);
    g_Wu[idx] = s;
    if (blockIdx.x == 0 && threadIdx.x < DM) {
        int t = threadIdx.x;
        float sb = bfp[t];
        for (int k = 0; k < DM; ++k) sb = fmaf(Wfp[t * DM + k], bip[k], sb);
        g_bu[t] = sb;
    }
}

// ---------------- K0b: compose W_c = in_proj @ W_u, b_c = in_proj @ b_u ----------
__global__ void k_combine2(const float* __restrict__ Win) {
    int idx = blockIdx.x * 256 + threadIdx.x;   // 128 blocks -> 32768 = 512*64
    int e = idx >> 6, i = idx & 63;
    float s = 0.f;
    for (int k = 0; k < DM; ++k) s = fmaf(Win[(long)e * DM + k], g_Wu[k * DMO + i], s);
    g_Wc[idx] = s;
    if (i == 0) {
        float sb = 0.f;
        for (int k = 0; k < DM; ++k) sb = fmaf(Win[(long)e * DM + k], g_bu[k], sb);
        g_bc[e] = sb;
    }
}

// ---------------- K1: rmsnorm1 + u = W_u @ xn + b_u ------------------------------
__global__ void __launch_bounds__(256, 3)
k_rms_u(const float* __restrict__ x, const float* __restrict__ wn1) {
    extern __shared__ float sm[];
    float* sx  = sm;                 // 64*68 [i][t]
    float* swT = sm + 64 * 68;       // 64*132 [i][o]  (+pad row for prefetch)
    float* ssc = swT + 65 * 132;     // 64
    int tid = threadIdx.x;
    long t0 = (long)blockIdx.x * 64;

    for (int idx = tid; idx < 64 * 64; idx += 256) {
        int i = idx & 63, t = idx >> 6;
        sx[i * 68 + t] = x[(t0 + t) * DMO + i];
    }
    for (int idx = tid; idx < DM * DMO; idx += 256) {
        int i = idx & 63, o = idx >> 6;
        swT[i * 132 + o] = g_Wu[o * DMO + i];
    }
    __syncthreads();
    if (tid < 64) {
        float ss = 0.f;
        for (int i = 0; i < DMO; ++i) { float v = sx[i * 68 + tid]; ss = fmaf(v, v, ss); }
        ssc[tid] = rsqrtf(ss * (1.f / DMO) + 1e-5f);
    }
    __syncthreads();
    for (int idx = tid; idx < 64 * 64; idx += 256) {
        int i = idx & 63, t = idx >> 6;
        float v = sx[i * 68 + t] * ssc[t] * wn1[i];
        sx[i * 68 + t] = v;
        g_xn[(t0 + t) * DMO + i] = v;
    }
    __syncthreads();
    int tx = tid & 31, ty = tid >> 5;
    ull acc[4][4] = {};
    float4 w4 = *(const float4*)&swT[tx << 2];
    ulonglong2 xa = *(const ulonglong2*)&sx[ty * 8];
    ulonglong2 xb = *(const ulonglong2*)&sx[ty * 8 + 4];
    #pragma unroll 8
    for (int i = 0; i < DMO; ++i) {
        ull wd0 = pk2(w4.x, w4.x), wd1 = pk2(w4.y, w4.y);
        ull wd2 = pk2(w4.z, w4.z), wd3 = pk2(w4.w, w4.w);
        ull x0 = xa.x, x1 = xa.y, x2 = xb.x, x3 = xb.y;
        w4 = *(const float4*)&swT[(i + 1) * 132 + (tx << 2)];
        xa = *(const ulonglong2*)&sx[(i + 1) * 68 + ty * 8];
        xb = *(const ulonglong2*)&sx[(i + 1) * 68 + ty * 8 + 4];
        FMA16(acc, x0, x1, x2, x3, wd0, wd1, wd2, wd3);
    }
    float4 bq = *(const float4*)&g_bu[tx << 2];
    #pragma unroll
    for (int p = 0; p < 4; ++p) {
        float2 v0 = upk(acc[p][0]), v1 = upk(acc[p][1]), v2 = upk(acc[p][2]), v3 = upk(acc[p][3]);
        long ta = t0 + ty * 8 + 2 * p, tb = ta + 1;
        float4 lo = make_float4(v0.x + bq.x, v1.x + bq.y, v2.x + bq.z, v3.x + bq.w);
        float4 hi = make_float4(v0.y + bq.x, v1.y + bq.y, v2.y + bq.z, v3.y + bq.w);
        *(float4*)&g_u[ta * DM + (tx << 2)] = lo;
        *(float4*)&g_u[tb * DM + (tx << 2)] = hi;
    }
}

// ---------------- K2: xz = W_c @ xn + b_c (tf32 MMA, permuted B layout) ----------
__global__ void __launch_bounds__(256, 3)
k_inproj(const float* __restrict__ cw, const float* __restrict__ cb) {
    extern __shared__ float sm[];
    float* sxn   = sm;                 // [i][permt(t)] 64*68 tf32 ; cols 64-66 halo
    float* swT   = sm + 64 * 68;       // [i][e] 64*132 tf32
    float* sbc   = sm + 12800 + 140;   // 128 biases (persists, fp32)
    float* stage = sm;                 // [e][t'] 128*68 AFTER GEMM (reuse)
    int tid = threadIdx.x;
    long t0 = (long)blockIdx.x * 64;
    int e0 = blockIdx.y * 128;
    int b = (int)(t0 >> 12);
    int l0 = (int)(t0 & (LSEQ - 1));
    bool isx = (e0 < DI);

    for (int idx = tid; idx < 64 * 64; idx += 256) {
        int i = idx & 63, t = idx >> 6;
        sxn[i * 68 + permt(t)] = tf32f(g_xn[(t0 + t) * DMO + i]);
    }
    for (int idx = tid; idx < 128 * 64; idx += 256) {
        int i = idx & 63, e = idx >> 6;
        swT[i * 132 + e] = tf32f(g_Wc[(long)(e0 + e) * DMO + i]);
    }
    if (tid < 128) sbc[tid] = g_bc[e0 + tid];
    if (isx && tid < 192) {   // halo xn: tokens t0-3..t0-1
        int i = tid & 63, j = tid >> 6;
        sxn[i * 68 + 64 + j] = (l0 > 0) ? tf32f(g_xn[(t0 - 3 + j) * DMO + i]) : 0.f;
    }
    __syncthreads();
    int warp = tid >> 5, lane = tid & 31, g = lane >> 2, tg = lane & 3;
    int ew = warp * 16;
    float c[8][4] = {};
    #pragma unroll
    for (int ks = 0; ks < 8; ++ks) {
        int kk = ks * 8;
        uint32_t a0 = __float_as_uint(swT[(kk + tg) * 132 + ew + g]);
        uint32_t a1 = __float_as_uint(swT[(kk + tg) * 132 + ew + g + 8]);
        uint32_t a2 = __float_as_uint(swT[(kk + tg + 4) * 132 + ew + g]);
        uint32_t a3 = __float_as_uint(swT[(kk + tg + 4) * 132 + ew + g + 8]);
        float4 q00 = *(const float4*)&sxn[(kk + tg) * 68 + g * 8];
        float4 q01 = *(const float4*)&sxn[(kk + tg) * 68 + g * 8 + 4];
        float4 q10 = *(const float4*)&sxn[(kk + tg + 4) * 68 + g * 8];
        float4 q11 = *(const float4*)&sxn[(kk + tg + 4) * 68 + g * 8 + 4];
        MMA_TF32(c[0], a0, a1, a2, a3, __float_as_uint(q00.x), __float_as_uint(q10.x));
        MMA_TF32(c[1], a0, a1, a2, a3, __float_as_uint(q00.y), __float_as_uint(q10.y));
        MMA_TF32(c[2], a0, a1, a2, a3, __float_as_uint(q00.z), __float_as_uint(q10.z));
        MMA_TF32(c[3], a0, a1, a2, a3, __float_as_uint(q00.w), __float_as_uint(q10.w));
        MMA_TF32(c[4], a0, a1, a2, a3, __float_as_uint(q01.x), __float_as_uint(q11.x));
        MMA_TF32(c[5], a0, a1, a2, a3, __float_as_uint(q01.y), __float_as_uint(q11.y));
        MMA_TF32(c[6], a0, a1, a2, a3, __float_as_uint(q01.z), __float_as_uint(q11.z));
        MMA_TF32(c[7], a0, a1, a2, a3, __float_as_uint(q01.w), __float_as_uint(q11.w));
    }
    // halo xz values -> registers (x blocks only); reads only halo cols 64-66
    float h1 = 0.f, h2 = 0.f;
    if (isx && l0 > 0) {
        {
            int j = tid >> 7, e = tid & 127;
            float a = sbc[e];
            for (int i = 0; i < 64; ++i)
                a = fmaf(sxn[i * 68 + 64 + j], swT[i * 132 + e], a);
            h1 = a;
        }
        if (tid < 128) {
            int e = tid;
            float a = sbc[e];
            for (int i = 0; i < 64; ++i)
                a = fmaf(sxn[i * 68 + 66], swT[i * 132 + e], a);
            h2 = a;
        }
    }
    __syncthreads();   // all reads of sxn/swT done -> reuse as stage
    {
        float bc0 = sbc[ew + g], bc1 = sbc[ew + g + 8];
        #pragma unroll
        for (int nt = 0; nt < 8; ++nt) {
            int t = nt * 8 + 2 * tg;
            stage[(ew + g) * 68 + 3 + t]     = c[nt][0] + bc0;
            stage[(ew + g) * 68 + 4 + t]     = c[nt][1] + bc0;
            stage[(ew + g + 8) * 68 + 3 + t] = c[nt][2] + bc1;
            stage[(ew + g + 8) * 68 + 4 + t] = c[nt][3] + bc1;
        }
    }
    if (isx) {
        { int j = tid >> 7, e = tid & 127; stage[e * 68 + j] = h1; }
        if (tid < 128) stage[tid * 68 + 2] = h2;
    }
    __syncthreads();
    if (isx) {
        for (int idx = tid; idx < 128 * 64; idx += 256) {
            int t = idx & 63, e = idx >> 6;
            int d = e0 + e;
            const float* st = &stage[e * 68];
            float4 w = *(const float4*)&cw[d * 4];
            float a = cb[d];
            a = fmaf(w.x, st[t], a);
            a = fmaf(w.y, st[t + 1], a);
            a = fmaf(w.z, st[t + 2], a);
            a = fmaf(w.w, st[t + 3], a);
            a = a / (1.f + __expf(-a));
            g_xc[(long)(b * DI + d) * LSEQ + l0 + t] = a;
        }
    } else {
        for (int idx = tid; idx < 128 * 64; idx += 256) {
            int t = idx & 63, e = idx >> 6;
            float v = stage[e * 68 + 3 + t];
            v = v / (1.f + __expf(-v));
            g_zs[(long)(b * DI + (e0 - DI) + e) * LSEQ + l0 + t] = v;
        }
    }
}

// ---------------- K4: x_dbl = x_proj @ x ; B,C ; delta (K-chunked, smem reuse) ---
__global__ void __launch_bounds__(256, 2)
k_xproj(const float* __restrict__ Xp, const float* __restrict__ Wdt,
        const float* __restrict__ bdt) {
    extern __shared__ float sm[];
    float* sdbl = sm;                 // 64*40 (persists)
    float* sxc  = sm + 2560;          // phase1: [t][kk] 64*132
    float* spc  = sm + 2560 + 8448;   // phase1: [e][kk] 40*132
    float* sdel = sm + 2560;          // phase2: [d][t] 256*65 (reuses chunk region)
    int tid = threadIdx.x;
    long t0 = (long)blockIdx.x * 64;
    int b = (int)(t0 >> 12);
    int l0 = (int)(t0 & (LSEQ - 1));

    int tt = tid >> 2, eb = (tid & 3) * 10;
    float acc[10] = {};
    for (int kc = 0; kc < 2; ++kc) {
        __syncthreads();
        for (int idx = tid; idx < 64 * 128; idx += 256) {
            int t = idx & 63, kk = idx >> 6;
            sxc[t * 132 + kk] = g_xc[(long)(b * DI + kc * 128 + kk) * LSEQ + l0 + t];
        }
        for (int idx = tid; idx < 40 * 128; idx += 256) {
            int kk = idx & 127, e = idx >> 7;
            spc[e * 132 + kk] = Xp[e * DI + kc * 128 + kk];
        }
        __syncthreads();
        for (int kk = 0; kk < 128; kk += 4) {
            float4 xv = *(const float4*)&sxc[tt * 132 + kk];
            #pragma unroll
            for (int e = 0; e < 10; ++e) {
                float4 wv = *(const float4*)&spc[(eb + e) * 132 + kk];
                acc[e] = fmaf(xv.x, wv.x, fmaf(xv.y, wv.y, fmaf(xv.z, wv.z, fmaf(xv.w, wv.w, acc[e]))));
            }
        }
    }
    __syncthreads();
    #pragma unroll
    for (int e = 0; e < 10; ++e) sdbl[tt * 40 + eb + e] = acc[e];
    __syncthreads();
    for (int idx = tid; idx < 64 * DS; idx += 256) {
        int t = idx >> 4, s = idx & 15;
        g_Bm[(t0 + t) * DS + s] = sdbl[t * 40 + 8 + s];
        g_Cm[(t0 + t) * DS + s] = sdbl[t * 40 + 24 + s];
    }
    {
        int d = tid;
        float wr[8];
        #pragma unroll
        for (int r = 0; r < 8; ++r) wr[r] = Wdt[d * 8 + r];
        float bb = bdt[d];
        for (int t = 0; t < 64; ++t) {
            float pre = bb;
            #pragma unroll
            for (int r = 0; r < 8; ++r) pre = fmaf(sdbl[t * 40 + r], wr[r], pre);
            float sp = (pre > 20.f) ? pre : log1pf(__expf(pre));
            sdel[d * 65 + t] = sp;
        }
    }
    __syncthreads();
    for (int idx = tid; idx < DI * 64; idx += 256) {
        int d = idx >> 6, t = idx & 63;
        g_delta[(long)(b * DI + d) * LSEQ + l0 + t] = sdel[d * 65 + t];
    }
}

// ---------------- K5a: per-chunk decay product P and local state q ----------------
__global__ void __launch_bounds__(256, 6)
k_scan1(const float* __restrict__ Alog) {
    int u = threadIdx.x >> 4;
    int s = threadIdx.x & 15;
    int unit = blockIdx.x * 16 + u;
    int g = unit & (NG - 1);
    int ch = unit >> 6;
    int b = ch >> 8, d = ch & 255;
    float Aval = -__expf(Alog[d * DS + s]);
    const float* pd = g_delta + (long)ch * LSEQ + g * CHK;
    const float* px = g_xc    + (long)ch * LSEQ + g * CHK;
    const float* pB = g_Bm    + ((long)b * LSEQ + g * CHK) * DS + s;
    float P = 1.f, q = 0.f;
    #pragma unroll 4
    for (int t = 0; t < CHK; t += 4) {
        float4 dv = *(const float4*)&pd[t];
        float4 xv = *(const float4*)&px[t];
        float B0 = pB[(t + 0) * DS], B1 = pB[(t + 1) * DS];
        float B2 = pB[(t + 2) * DS], B3 = pB[(t + 3) * DS];
        float a0 = __expf(dv.x * Aval); P *= a0; q = fmaf(a0, q, dv.x * xv.x * B0);
        float a1 = __expf(dv.y * Aval); P *= a1; q = fmaf(a1, q, dv.y * xv.y * B1);
        float a2 = __expf(dv.z * Aval); P *= a2; q = fmaf(a2, q, dv.z * xv.z * B2);
        float a3 = __expf(dv.w * Aval); P *= a3; q = fmaf(a3, q, dv.w * xv.w * B3);
    }
    long idx = (long)unit * DS + s;
    g_P[idx] = P;
    g_q[idx] = q;
}

// ---------------- K5b: propagate h_in across chunks ------------------------------
__global__ void k_scan2() {
    int tid = blockIdx.x * 256 + threadIdx.x;
    int ch = tid >> 4, s = tid & 15;
    float h = 0.f;
    long base = (long)ch * NG * DS + s;
    #pragma unroll 8
    for (int g = 0; g < NG; ++g) {
        long idx = base + (long)g * DS;
        g_hin[idx] = h;
        h = fmaf(g_P[idx], h, g_q[idx]);
    }
}

// ---------------- K5c: local scan from h_in, y = (C.h + x*D) * silu(z) -----------
__global__ void __launch_bounds__(256, 6)
k_scan3(const float* __restrict__ Alog, const float* __restrict__ Dp_) {
    __shared__ float ybuf[16 * CHK];
    int u = threadIdx.x >> 4;
    int s = threadIdx.x & 15;
    int unit = blockIdx.x * 16 + u;
    int g = unit & (NG - 1);
    int ch = unit >> 6;
    int b = ch >> 8, d = ch & 255;
    float Aval = -__expf(Alog[d * DS + s]);
    float Dp = Dp_[d];
    const float* pd = g_delta + (long)ch * LSEQ + g * CHK;
    const float* px = g_xc    + (long)ch * LSEQ + g * CHK;
    const float* pz = g_zs    + (long)ch * LSEQ + g * CHK;
    const float* pB = g_Bm    + ((long)b * LSEQ + g * CHK) * DS + s;
    const float* pC = g_Cm    + ((long)b * LSEQ + g * CHK) * DS + s;
    float h = g_hin[(long)unit * DS + s];
    #pragma unroll 2
    for (int t = 0; t < CHK; t += 4) {
        float4 dv = *(const float4*)&pd[t];
        float4 xv = *(const float4*)&px[t];
        float4 zv;
        if (s == 0) zv = *(const float4*)&pz[t];
        #pragma unroll
        for (int j = 0; j < 4; ++j) {
            float dvj = (j == 0) ? dv.x : (j == 1) ? dv.y : (j == 2) ? dv.z : dv.w;
            float xvj = (j == 0) ? xv.x : (j == 1) ? xv.y : (j == 2) ? xv.z : xv.w;
            float Bv = pB[(t + j) * DS];
            float Cv = pC[(t + j) * DS];
            float a = __expf(dvj * Aval);
            h = fmaf(a, h, dvj * xvj * Bv);
            float p = h * Cv;
            p += __shfl_xor_sync(0xffffffffu, p, 8);
            p += __shfl_xor_sync(0xffffffffu, p, 4);
            p += __shfl_xor_sync(0xffffffffu, p, 2);
            p += __shfl_xor_sync(0xffffffffu, p, 1);
            if (s == 0) {
                float zvj = (j == 0) ? zv.x : (j == 1) ? zv.y : (j == 2) ? zv.z : zv.w;
                ybuf[u * CHK + t + j] = (p + xvj * Dp) * zvj;
            }
        }
    }
    __syncthreads();
    float* py = g_y + (long)ch * LSEQ + (long)(blockIdx.x & 3) * 1024;
    for (int i = threadIdx.x; i < 16 * CHK; i += 256) py[i] = ybuf[i];
}

// ---------------- K6: FUSED outproj + final --------------------------------------
// m = rmsnorm2(Wmo @ y) + u  (tf32 MMA, m kept in smem)
// w = swish(Wwp @ xn + bwp) ; out = Wop @ (w*m) + bop + x
__global__ void __launch_bounds__(256, 2)
k_outfin(const float* __restrict__ Wmo, const float* __restrict__ wn2,
         const float* __restrict__ Wwp, const float* __restrict__ bwp,
         const float* __restrict__ Wop, const float* __restrict__ bop,
         const float* __restrict__ x, float* __restrict__ out) {
    extern __shared__ float sm[];
    float* syT  = sm;               // 64*68 [k][permt(t)] y chunk ; later sxn [i][t]
    float* swT  = sm + 4352;        // 64*132 [k][o] Wmo chunk ; later stage/smm [t][132]
    float* swpT = sm + 12800;       // 8704 floats: swpT [i][c] 64*132 ; later sopT [c][o] 128*68
    int tid = threadIdx.x;
    long t0 = (long)blockIdx.x * 64;
    int b = (int)(t0 >> 12);
    int lpos = (int)(t0 & (LSEQ - 1));
    int warp = tid >> 5, lane = tid & 31, g = lane >> 2, tg = lane & 3;
    int o0 = warp * 16;

    // -------- phase 1: mamba_out GEMM (tf32 MMA, K-chunked) --------
    float c[8][4] = {};
    for (int kc = 0; kc < 4; ++kc) {
        __syncthreads();
        for (int idx = tid; idx < 64 * 16; idx += 256) {
            int t4 = idx & 15, k = idx >> 4;
            float4 v = *(const float4*)&g_y[(long)(b * DI + kc * 64 + k) * LSEQ + lpos + t4 * 4];
            int tb = t4 * 4;
            syT[k * 68 + permt(tb + 0)] = tf32f(v.x);
            syT[k * 68 + permt(tb + 1)] = tf32f(v.y);
            syT[k * 68 + permt(tb + 2)] = tf32f(v.z);
            syT[k * 68 + permt(tb + 3)] = tf32f(v.w);
        }
        for (int idx = tid; idx < 64 * DM; idx += 256) {
            int k = idx & 63, o = idx >> 6;
            swT[k * 132 + o] = tf32f(Wmo[(long)o * DI + kc * 64 + k]);
        }
        __syncthreads();
        #pragma unroll
        for (int ks = 0; ks < 8; ++ks) {
            int kk = ks * 8;
            uint32_t a0 = __float_as_uint(swT[(kk + tg) * 132 + o0 + g]);
            uint32_t a1 = __float_as_uint(swT[(kk + tg) * 132 + o0 + g + 8]);
            uint32_t a2 = __float_as_uint(swT[(kk + tg + 4) * 132 + o0 + g]);
            uint32_t a3 = __float_as_uint(swT[(kk + tg + 4) * 132 + o0 + g + 8]);
            float4 q00 = *(const float4*)&syT[(kk + tg) * 68 + g * 8];
            float4 q01 = *(const float4*)&syT[(kk + tg) * 68 + g * 8 + 4];
            float4 q10 = *(const float4*)&syT[(kk + tg + 4) * 68 + g * 8];
            float4 q11 = *(const float4*)&syT[(kk + tg + 4) * 68 + g * 8 + 4];
            MMA_TF32(c[0], a0, a1, a2, a3, __float_as_uint(q00.x), __float_as_uint(q10.x));
            MMA_TF32(c[1], a0, a1, a2, a3, __float_as_uint(q00.y), __float_as_uint(q10.y));
            MMA_TF32(c[2], a0, a1, a2, a3, __float_as_uint(q00.z), __float_as_uint(q10.z));
            MMA_TF32(c[3], a0, a1, a2, a3, __float_as_uint(q00.w), __float_as_uint(q10.w));
            MMA_TF32(c[4], a0, a1, a2, a3, __float_as_uint(q01.x), __float_as_uint(q11.x));
            MMA_TF32(c[5], a0, a1, a2, a3, __float_as_uint(q01.y), __float_as_uint(q11.y));
            MMA_TF32(c[6], a0, a1, a2, a3, __float_as_uint(q01.z), __float_as_uint(q11.z));
            MMA_TF32(c[7], a0, a1, a2, a3, __float_as_uint(q01.w), __float_as_uint(q11.w));
        }
    }
    __syncthreads();   // syT/swT reads done -> reuse
    float* stage = swT;     // [t][132]
    float* sxn   = syT;     // [i][t] 64*68
    // write fragments; fill sxn and swpT (independent regions)
    #pragma unroll
    for (int nt = 0; nt < 8; ++nt) {
        int t = nt * 8 + 2 * tg;
        stage[t * 132 + o0 + g]           = c[nt][0];
        stage[(t + 1) * 132 + o0 + g]     = c[nt][1];
        stage[t * 132 + o0 + g + 8]       = c[nt][2];
        stage[(t + 1) * 132 + o0 + g + 8] = c[nt][3];
    }
    for (int idx = tid; idx < 64 * 64; idx += 256) {
        int i = idx & 63, t = idx >> 6;
        sxn[i * 68 + t] = g_xn[(t0 + t) * DMO + i];
    }
    for (int idx = tid; idx < DM * DMO; idx += 256) {
        int i = idx & 63, cc = idx >> 6;
        swpT[i * 132 + cc] = Wwp[cc * DMO + i];
    }
    __syncthreads();
    // -------- rmsnorm2 + u residual, in place in stage --------
    {
        int t = tid >> 2, part = tid & 3;
        int ob = part * 32;
        float ss = 0.f;
        #pragma unroll
        for (int j = 0; j < 32; j += 4) {
            float4 v = *(const float4*)&stage[t * 132 + ob + j];
            ss = fmaf(v.x, v.x, fmaf(v.y, v.y, fmaf(v.z, v.z, fmaf(v.w, v.w, ss))));
        }
        ss += __shfl_xor_sync(0xffffffffu, ss, 1);
        ss += __shfl_xor_sync(0xffffffffu, ss, 2);
        float sc = rsqrtf(ss * (1.f / DM) + 1e-5f);
        long tt = t0 + t;
        #pragma unroll
        for (int j = 0; j < 32; j += 4) {
            float4 v  = *(const float4*)&stage[t * 132 + ob + j];
            float4 w2 = *(const float4*)&wn2[ob + j];
            float4 uq = *(const float4*)&g_u[tt * DM + ob + j];
            float4 ov = make_float4(v.x * sc * w2.x + uq.x, v.y * sc * w2.y + uq.y,
                                    v.z * sc * w2.z + uq.z, v.w * sc * w2.w + uq.w);
            *(float4*)&stage[t * 132 + ob + j] = ov;
        }
    }
    __syncthreads();
    // -------- phase 2: w = swish(Wwp @ xn + bwp), gate m in place --------
    int tx = tid & 31, ty = tid >> 5;
    float* smm = stage;
    {
        ull acc[4][4] = {};
        float4 w4 = *(const float4*)&swpT[tx << 2];
        ulonglong2 xa = *(const ulonglong2*)&sxn[ty * 8];
        ulonglong2 xb = *(const ulonglong2*)&sxn[ty * 8 + 4];
        #pragma unroll 8
        for (int i = 0; i < DMO; ++i) {
            ull wd0 = pk2(w4.x, w4.x), wd1 = pk2(w4.y, w4.y);
            ull wd2 = pk2(w4.z, w4.z), wd3 = pk2(w4.w, w4.w);
            ull x0 = xa.x, x1 = xa.y, x2 = xb.x, x3 = xb.y;
            // prefetch i+1: swpT row 64 reads within 8704-float region (in-bounds);
            // sxn row 64 bleeds into stage region (value discarded) -- in-bounds of smem
            w4 = *(const float4*)&swpT[(i + 1) * 132 + (tx << 2)];
            xa = *(const ulonglong2*)&sxn[(i + 1) * 68 + ty * 8];
            xb = *(const ulonglong2*)&sxn[(i + 1) * 68 + ty * 8 + 4];
            FMA16(acc, x0, x1, x2, x3, wd0, wd1, wd2, wd3);
        }
        float4 bq = *(const float4*)&bwp[tx << 2];
        float bj[4] = {bq.x, bq.y, bq.z, bq.w};
        #pragma unroll
        for (int p = 0; p < 4; ++p)
            #pragma unroll
            for (int j = 0; j < 4; ++j) {
                float2 v = upk(acc[p][j]);
                int cc = (tx << 2) + j;
                int ta = ty * 8 + 2 * p;
                float va = v.x + bj[j], vb = v.y + bj[j];
                float wa = va / (1.f + __expf(-va));
                float wb = vb / (1.f + __expf(-vb));
                smm[ta * 132 + cc] *= wa;
                smm[(ta + 1) * 132 + cc] *= wb;
            }
    }
    __syncthreads();   // sxn/swpT dead -> load sopT over swpT region
    float* sopT = swpT;    // [c][o] 128*68 = 8704 floats
    for (int idx = tid; idx < DMO * DM; idx += 256) {
        int cc = idx & 127, o = idx >> 7;
        sopT[cc * 68 + o] = Wop[o * DM + cc];
    }
    __syncthreads();
    // -------- phase 3: out = Wop @ (w*m) + bop + x --------
    {
        int rowg = tid >> 4;
        int o4 = (tid & 15) << 2;
        float a2[4][4] = {};
        for (int cc = 0; cc < DM; cc += 4) {
            float4 q0 = *(const float4*)&sopT[(cc + 0) * 68 + o4];
            float4 q1 = *(const float4*)&sopT[(cc + 1) * 68 + o4];
            float4 q2 = *(const float4*)&sopT[(cc + 2) * 68 + o4];
            float4 q3 = *(const float4*)&sopT[(cc + 3) * 68 + o4];
            #pragma unroll
            for (int rr = 0; rr < 4; ++rr) {
                float4 pv = *(const float4*)&smm[(rowg * 4 + rr) * 132 + cc];
                a2[rr][0] = fmaf(pv.x, q0.x, fmaf(pv.y, q1.x, fmaf(pv.z, q2.x, fmaf(pv.w, q3.x, a2[rr][0]))));
                a2[rr][1] = fmaf(pv.x, q0.y, fmaf(pv.y, q1.y, fmaf(pv.z, q2.y, fmaf(pv.w, q3.y, a2[rr][1]))));
                a2[rr][2] = fmaf(pv.x, q0.z, fmaf(pv.y, q1.z, fmaf(pv.z, q2.z, fmaf(pv.w, q3.z, a2[rr][2]))));
                a2[rr][3] = fmaf(pv.x, q0.w, fmaf(pv.y, q1.w, fmaf(pv.z, q2.w, fmaf(pv.w, q3.w, a2[rr][3]))));
            }
        }
        float4 bq = *(const float4*)&bop[o4];
        #pragma unroll
        for (int rr = 0; rr < 4; ++rr) {
            long tg2 = t0 + rowg * 4 + rr;
            float4 xq = *(const float4*)&x[tg2 * DMO + o4];
            float4 ov = make_float4(a2[rr][0] + bq.x + xq.x, a2[rr][1] + bq.y + xq.y,
                                    a2[rr][2] + bq.z + xq.z, a2[rr][3] + bq.w + xq.w);
            *(float4*)&out[tg2 * DMO + o4] = ov;
        }
    }
}

// ---------------- launch -----------------------------------------------------------
extern "C" void kernel_launch(void* const* d_in, const int* in_sizes, int n_in,
                              void* d_out, int out_size) {
    const float* x    = (const float*)d_in[0];
    const float* wn1  = (const float*)d_in[1];
    const float* wn2  = (const float*)d_in[2];
    const float* Wip  = (const float*)d_in[3];
    const float* bip  = (const float*)d_in[4];
    const float* Wfp  = (const float*)d_in[5];
    const float* bfp  = (const float*)d_in[6];
    const float* Wwp  = (const float*)d_in[7];
    const float* bwp  = (const float*)d_in[8];
    const float* Wop  = (const float*)d_in[9];
    const float* bop  = (const float*)d_in[10];
    const float* Win  = (const float*)d_in[11];
    const float* cw   = (const float*)d_in[12];
    const float* cb   = (const float*)d_in[13];
    const float* Xp   = (const float*)d_in[14];
    const float* Wdt  = (const float*)d_in[15];
    const float* bdt  = (const float*)d_in[16];
    const float* Alog = (const float*)d_in[17];
    const float* Dpar = (const float*)d_in[18];
    const float* Wmo  = (const float*)d_in[19];
    float* out = (float*)d_out;

    const int SM_K1 = (64 * 68 + 65 * 132 + 64 + 16) * 4;
    const int SM_K2 = (12800 + 140 + 128 + 16) * 4;
    const int SM_K4 = (2560 + 256 * 65) * 4;
    const int SM_KOF = (4352 + 8448 + 8704) * 4;   // 86016 B -> 2 CTA/SM

    cudaFuncSetAttribute(k_rms_u,   cudaFuncAttributeMaxDynamicSharedMemorySize, SM_K1);
    cudaFuncSetAttribute(k_inproj,  cudaFuncAttributeMaxDynamicSharedMemorySize, SM_K2);
    cudaFuncSetAttribute(k_xproj,   cudaFuncAttributeMaxDynamicSharedMemorySize, SM_K4);
    cudaFuncSetAttribute(k_outfin,  cudaFuncAttributeMaxDynamicSharedMemorySize, SM_KOF);

    k_combine<<<32, 256>>>(Wfp, Wip, bip, bfp);
    k_combine2<<<128, 256>>>(Win);
    k_rms_u<<<TOK / 64, 256, SM_K1>>>(x, wn1);
    k_inproj<<<dim3(TOK / 64, 4), 256, SM_K2>>>(cw, cb);
    k_xproj<<<TOK / 64, 256, SM_K4>>>(Xp, Wdt, bdt);
    k_scan1<<<NUNIT / 16, 256>>>(Alog);
    k_scan2<<<64, 256>>>();
    k_scan3<<<NUNIT / 16, 256>>>(Alog, Dpar);
    k_outfin<<<TOK / 64, 256, SM_KOF>>>(Wmo, wn2, Wwp, bwp, Wop, bop, x, out);
}

// round 14
// speedup vs baseline: 1.1089x; 1.0707x over previous
#include <cuda_runtime.h>
#include <cstdint>

#define TOK 16384
#define LSEQ 4096
#define NB 4
#define DMO 64      // input/output dim D
#define DM 128      // d_model of mamba (2D)
#define DI 256      // d_inner
#define DS 16       // d_state
#define DTR 8       // dt_rank
#define NCH 1024    // NB * DI channels
#define CHK 64      // chunk length
#define NG (LSEQ / CHK)   // 64 chunks

typedef unsigned long long ull;

__device__ __forceinline__ ull pk2(float a, float b) {
    ull r; asm("mov.b64 %0, {%1, %2};" : "=l"(r) : "f"(a), "f"(b)); return r;
}
__device__ __forceinline__ void fma2(ull& d, ull a, ull b) {
    asm("fma.rn.f32x2 %0, %1, %2, %3;" : "=l"(d) : "l"(a), "l"(b), "l"(d));
}
__device__ __forceinline__ float2 upk(ull v) {
    float2 r; asm("mov.b64 {%0, %1}, %2;" : "=f"(r.x), "=f"(r.y) : "l"(v)); return r;
}
__device__ __forceinline__ uint32_t tf32c(float f) {
    uint32_t r; asm("cvt.rna.tf32.f32 %0, %1;" : "=r"(r) : "f"(f)); return r;
}
__device__ __forceinline__ float tf32f(float f) {
    return __uint_as_float(tf32c(f));
}
__device__ __forceinline__ int permt(int t) { return ((t & 7) << 3) | (t >> 3); }

#define MMA_TF32(c, a0, a1, a2, a3, b0, b1) \
    asm volatile("mma.sync.aligned.m16n8k8.row.col.f32.tf32.tf32.f32 " \
        "{%0,%1,%2,%3}, {%4,%5,%6,%7}, {%8,%9}, {%0,%1,%2,%3};" \
        : "+f"((c)[0]), "+f"((c)[1]), "+f"((c)[2]), "+f"((c)[3]) \
        : "r"(a0), "r"(a1), "r"(a2), "r"(a3), "r"(b0), "r"(b1))

#define FMA16(acc, x0, x1, x2, x3, wd0, wd1, wd2, wd3) \
    fma2(acc[0][0], x0, wd0); fma2(acc[0][1], x0, wd1); fma2(acc[0][2], x0, wd2); fma2(acc[0][3], x0, wd3); \
    fma2(acc[1][0], x1, wd0); fma2(acc[1][1], x1, wd1); fma2(acc[1][2], x1, wd2); fma2(acc[1][3], x1, wd3); \
    fma2(acc[2][0], x2, wd0); fma2(acc[2][1], x2, wd1); fma2(acc[2][2], x2, wd2); fma2(acc[2][3], x2, wd3); \
    fma2(acc[3][0], x3, wd0); fma2(acc[3][1], x3, wd1); fma2(acc[3][2], x3, wd2); fma2(acc[3][3], x3, wd3)

// ---------------- scratch ----------------
// xc / zs / delta / y are CHANNEL-MAJOR: [(b*DI + d) * LSEQ + l]
__device__ float g_Wu[DM * DMO];      // W_fp @ W_ip
__device__ float g_bu[DM];            // W_fp @ b_ip + b_fp
__device__ float g_Wc[2 * DI * DMO];  // in_proj @ W_u   (512 x 64)
__device__ float g_bc[2 * DI];        // in_proj @ b_u
__device__ float g_xn[TOK * DMO];
__device__ float g_u[TOK * DM];
__device__ float g_xc[NCH * LSEQ];
__device__ float g_zs[NCH * LSEQ];
__device__ float g_delta[NCH * LSEQ];
__device__ float g_Bm[TOK * DS];
__device__ float g_Cm[TOK * DS];
__device__ float g_y[NCH * LSEQ];

// ---------------- K0: compose W_u = W_fp @ W_ip, b_u = W_fp@b_ip + b_fp ----------
__global__ void k_combine(const float* __restrict__ Wfp, const float* __restrict__ Wip,
                          const float* __restrict__ bip, const float* __restrict__ bfp) {
    int idx = blockIdx.x * 256 + threadIdx.x;
    int o = idx / DMO, i = idx % DMO;
    float s = 0.f;
    for (int k = 0; k < DM; ++k) s = fmaf(Wfp[o * DM + k], Wip[k * DMO + i], s);
    g_Wu[idx] = s;
    if (blockIdx.x == 0 && threadIdx.x < DM) {
        int t = threadIdx.x;
        float sb = bfp[t];
        for (int k = 0; k < DM; ++k) sb = fmaf(Wfp[t * DM + k], bip[k], sb);
        g_bu[t] = sb;
    }
}

// ---------------- K0b: compose W_c = in_proj @ W_u, b_c = in_proj @ b_u ----------
__global__ void k_combine2(const float* __restrict__ Win) {
    int idx = blockIdx.x * 256 + threadIdx.x;
    int e = idx >> 6, i = idx & 63;
    float s = 0.f;
    for (int k = 0; k < DM; ++k) s = fmaf(Win[(long)e * DM + k], g_Wu[k * DMO + i], s);
    g_Wc[idx] = s;
    if (i == 0) {
        float sb = 0.f;
        for (int k = 0; k < DM; ++k) sb = fmaf(Win[(long)e * DM + k], g_bu[k], sb);
        g_bc[e] = sb;
    }
}

// ---------------- K1: rmsnorm1 + u = W_u @ xn + b_u ------------------------------
__global__ void __launch_bounds__(256, 3)
k_rms_u(const float* __restrict__ x, const float* __restrict__ wn1) {
    extern __shared__ float sm[];
    float* sx  = sm;                 // 64*68 [i][t]
    float* swT = sm + 64 * 68;       // 64*132 [i][o]  (+pad row for prefetch)
    float* ssc = swT + 65 * 132;     // 64
    int tid = threadIdx.x;
    long t0 = (long)blockIdx.x * 64;

    for (int idx = tid; idx < 64 * 64; idx += 256) {
        int i = idx & 63, t = idx >> 6;
        sx[i * 68 + t] = x[(t0 + t) * DMO + i];
    }
    for (int idx = tid; idx < DM * DMO; idx += 256) {
        int i = idx & 63, o = idx >> 6;
        swT[i * 132 + o] = g_Wu[o * DMO + i];
    }
    __syncthreads();
    if (tid < 64) {
        float ss = 0.f;
        for (int i = 0; i < DMO; ++i) { float v = sx[i * 68 + tid]; ss = fmaf(v, v, ss); }
        ssc[tid] = rsqrtf(ss * (1.f / DMO) + 1e-5f);
    }
    __syncthreads();
    for (int idx = tid; idx < 64 * 64; idx += 256) {
        int i = idx & 63, t = idx >> 6;
        float v = sx[i * 68 + t] * ssc[t] * wn1[i];
        sx[i * 68 + t] = v;
        g_xn[(t0 + t) * DMO + i] = v;
    }
    __syncthreads();
    int tx = tid & 31, ty = tid >> 5;
    ull acc[4][4] = {};
    float4 w4 = *(const float4*)&swT[tx << 2];
    ulonglong2 xa = *(const ulonglong2*)&sx[ty * 8];
    ulonglong2 xb = *(const ulonglong2*)&sx[ty * 8 + 4];
    #pragma unroll 8
    for (int i = 0; i < DMO; ++i) {
        ull wd0 = pk2(w4.x, w4.x), wd1 = pk2(w4.y, w4.y);
        ull wd2 = pk2(w4.z, w4.z), wd3 = pk2(w4.w, w4.w);
        ull x0 = xa.x, x1 = xa.y, x2 = xb.x, x3 = xb.y;
        w4 = *(const float4*)&swT[(i + 1) * 132 + (tx << 2)];
        xa = *(const ulonglong2*)&sx[(i + 1) * 68 + ty * 8];
        xb = *(const ulonglong2*)&sx[(i + 1) * 68 + ty * 8 + 4];
        FMA16(acc, x0, x1, x2, x3, wd0, wd1, wd2, wd3);
    }
    float4 bq = *(const float4*)&g_bu[tx << 2];
    #pragma unroll
    for (int p = 0; p < 4; ++p) {
        float2 v0 = upk(acc[p][0]), v1 = upk(acc[p][1]), v2 = upk(acc[p][2]), v3 = upk(acc[p][3]);
        long ta = t0 + ty * 8 + 2 * p, tb = ta + 1;
        float4 lo = make_float4(v0.x + bq.x, v1.x + bq.y, v2.x + bq.z, v3.x + bq.w);
        float4 hi = make_float4(v0.y + bq.x, v1.y + bq.y, v2.y + bq.z, v3.y + bq.w);
        *(float4*)&g_u[ta * DM + (tx << 2)] = lo;
        *(float4*)&g_u[tb * DM + (tx << 2)] = hi;
    }
}

// ---------------- K2: xz = W_c @ xn + b_c (tf32 MMA, permuted B layout) ----------
__global__ void __launch_bounds__(256, 3)
k_inproj(const float* __restrict__ cw, const float* __restrict__ cb) {
    extern __shared__ float sm[];
    float* sxn   = sm;                 // [i][permt(t)] 64*68 tf32 ; cols 64-66 halo
    float* swT   = sm + 64 * 68;       // [i][e] 64*132 tf32
    float* sbc   = sm + 12800 + 140;   // 128 biases (persists, fp32)
    float* stage = sm;                 // [e][t'] 128*68 AFTER GEMM (reuse)
    int tid = threadIdx.x;
    long t0 = (long)blockIdx.x * 64;
    int e0 = blockIdx.y * 128;
    int b = (int)(t0 >> 12);
    int l0 = (int)(t0 & (LSEQ - 1));
    bool isx = (e0 < DI);

    for (int idx = tid; idx < 64 * 64; idx += 256) {
        int i = idx & 63, t = idx >> 6;
        sxn[i * 68 + permt(t)] = tf32f(g_xn[(t0 + t) * DMO + i]);
    }
    for (int idx = tid; idx < 128 * 64; idx += 256) {
        int i = idx & 63, e = idx >> 6;
        swT[i * 132 + e] = tf32f(g_Wc[(long)(e0 + e) * DMO + i]);
    }
    if (tid < 128) sbc[tid] = g_bc[e0 + tid];
    if (isx && tid < 192) {
        int i = tid & 63, j = tid >> 6;
        sxn[i * 68 + 64 + j] = (l0 > 0) ? tf32f(g_xn[(t0 - 3 + j) * DMO + i]) : 0.f;
    }
    __syncthreads();
    int warp = tid >> 5, lane = tid & 31, g = lane >> 2, tg = lane & 3;
    int ew = warp * 16;
    float c[8][4] = {};
    #pragma unroll
    for (int ks = 0; ks < 8; ++ks) {
        int kk = ks * 8;
        uint32_t a0 = __float_as_uint(swT[(kk + tg) * 132 + ew + g]);
        uint32_t a1 = __float_as_uint(swT[(kk + tg) * 132 + ew + g + 8]);
        uint32_t a2 = __float_as_uint(swT[(kk + tg + 4) * 132 + ew + g]);
        uint32_t a3 = __float_as_uint(swT[(kk + tg + 4) * 132 + ew + g + 8]);
        float4 q00 = *(const float4*)&sxn[(kk + tg) * 68 + g * 8];
        float4 q01 = *(const float4*)&sxn[(kk + tg) * 68 + g * 8 + 4];
        float4 q10 = *(const float4*)&sxn[(kk + tg + 4) * 68 + g * 8];
        float4 q11 = *(const float4*)&sxn[(kk + tg + 4) * 68 + g * 8 + 4];
        MMA_TF32(c[0], a0, a1, a2, a3, __float_as_uint(q00.x), __float_as_uint(q10.x));
        MMA_TF32(c[1], a0, a1, a2, a3, __float_as_uint(q00.y), __float_as_uint(q10.y));
        MMA_TF32(c[2], a0, a1, a2, a3, __float_as_uint(q00.z), __float_as_uint(q10.z));
        MMA_TF32(c[3], a0, a1, a2, a3, __float_as_uint(q00.w), __float_as_uint(q10.w));
        MMA_TF32(c[4], a0, a1, a2, a3, __float_as_uint(q01.x), __float_as_uint(q11.x));
        MMA_TF32(c[5], a0, a1, a2, a3, __float_as_uint(q01.y), __float_as_uint(q11.y));
        MMA_TF32(c[6], a0, a1, a2, a3, __float_as_uint(q01.z), __float_as_uint(q11.z));
        MMA_TF32(c[7], a0, a1, a2, a3, __float_as_uint(q01.w), __float_as_uint(q11.w));
    }
    float h1 = 0.f, h2 = 0.f;
    if (isx && l0 > 0) {
        {
            int j = tid >> 7, e = tid & 127;
            float a = sbc[e];
            for (int i = 0; i < 64; ++i)
                a = fmaf(sxn[i * 68 + 64 + j], swT[i * 132 + e], a);
            h1 = a;
        }
        if (tid < 128) {
            int e = tid;
            float a = sbc[e];
            for (int i = 0; i < 64; ++i)
                a = fmaf(sxn[i * 68 + 66], swT[i * 132 + e], a);
            h2 = a;
        }
    }
    __syncthreads();
    {
        float bc0 = sbc[ew + g], bc1 = sbc[ew + g + 8];
        #pragma unroll
        for (int nt = 0; nt < 8; ++nt) {
            int t = nt * 8 + 2 * tg;
            stage[(ew + g) * 68 + 3 + t]     = c[nt][0] + bc0;
            stage[(ew + g) * 68 + 4 + t]     = c[nt][1] + bc0;
            stage[(ew + g + 8) * 68 + 3 + t] = c[nt][2] + bc1;
            stage[(ew + g + 8) * 68 + 4 + t] = c[nt][3] + bc1;
        }
    }
    if (isx) {
        { int j = tid >> 7, e = tid & 127; stage[e * 68 + j] = h1; }
        if (tid < 128) stage[tid * 68 + 2] = h2;
    }
    __syncthreads();
    if (isx) {
        for (int idx = tid; idx < 128 * 64; idx += 256) {
            int t = idx & 63, e = idx >> 6;
            int d = e0 + e;
            const float* st = &stage[e * 68];
            float4 w = *(const float4*)&cw[d * 4];
            float a = cb[d];
            a = fmaf(w.x, st[t], a);
            a = fmaf(w.y, st[t + 1], a);
            a = fmaf(w.z, st[t + 2], a);
            a = fmaf(w.w, st[t + 3], a);
            a = a / (1.f + __expf(-a));
            g_xc[(long)(b * DI + d) * LSEQ + l0 + t] = a;
        }
    } else {
        for (int idx = tid; idx < 128 * 64; idx += 256) {
            int t = idx & 63, e = idx >> 6;
            float v = stage[e * 68 + 3 + t];
            v = v / (1.f + __expf(-v));
            g_zs[(long)(b * DI + (e0 - DI) + e) * LSEQ + l0 + t] = v;
        }
    }
}

// ---------------- K4: x_dbl = x_proj @ x ; B,C ; delta (K-chunked, smem reuse) ---
__global__ void __launch_bounds__(256, 2)
k_xproj(const float* __restrict__ Xp, const float* __restrict__ Wdt,
        const float* __restrict__ bdt) {
    extern __shared__ float sm[];
    float* sdbl = sm;                 // 64*40 (persists)
    float* sxc  = sm + 2560;          // phase1: [t][kk] 64*132
    float* spc  = sm + 2560 + 8448;   // phase1: [e][kk] 40*132
    float* sdel = sm + 2560;          // phase2: [d][t] 256*65
    int tid = threadIdx.x;
    long t0 = (long)blockIdx.x * 64;
    int b = (int)(t0 >> 12);
    int l0 = (int)(t0 & (LSEQ - 1));

    int tt = tid >> 2, eb = (tid & 3) * 10;
    float acc[10] = {};
    for (int kc = 0; kc < 2; ++kc) {
        __syncthreads();
        for (int idx = tid; idx < 64 * 128; idx += 256) {
            int t = idx & 63, kk = idx >> 6;
            sxc[t * 132 + kk] = g_xc[(long)(b * DI + kc * 128 + kk) * LSEQ + l0 + t];
        }
        for (int idx = tid; idx < 40 * 128; idx += 256) {
            int kk = idx & 127, e = idx >> 7;
            spc[e * 132 + kk] = Xp[e * DI + kc * 128 + kk];
        }
        __syncthreads();
        for (int kk = 0; kk < 128; kk += 4) {
            float4 xv = *(const float4*)&sxc[tt * 132 + kk];
            #pragma unroll
            for (int e = 0; e < 10; ++e) {
                float4 wv = *(const float4*)&spc[(eb + e) * 132 + kk];
                acc[e] = fmaf(xv.x, wv.x, fmaf(xv.y, wv.y, fmaf(xv.z, wv.z, fmaf(xv.w, wv.w, acc[e]))));
            }
        }
    }
    __syncthreads();
    #pragma unroll
    for (int e = 0; e < 10; ++e) sdbl[tt * 40 + eb + e] = acc[e];
    __syncthreads();
    for (int idx = tid; idx < 64 * DS; idx += 256) {
        int t = idx >> 4, s = idx & 15;
        g_Bm[(t0 + t) * DS + s] = sdbl[t * 40 + 8 + s];
        g_Cm[(t0 + t) * DS + s] = sdbl[t * 40 + 24 + s];
    }
    {
        int d = tid;
        float wr[8];
        #pragma unroll
        for (int r = 0; r < 8; ++r) wr[r] = Wdt[d * 8 + r];
        float bb = bdt[d];
        for (int t = 0; t < 64; ++t) {
            float pre = bb;
            #pragma unroll
            for (int r = 0; r < 8; ++r) pre = fmaf(sdbl[t * 40 + r], wr[r], pre);
            float sp = (pre > 20.f) ? pre : log1pf(__expf(pre));
            sdel[d * 65 + t] = sp;
        }
    }
    __syncthreads();
    for (int idx = tid; idx < DI * 64; idx += 256) {
        int d = idx >> 6, t = idx & 63;
        g_delta[(long)(b * DI + d) * LSEQ + l0 + t] = sdel[d * 65 + t];
    }
}

// ---------------- K5: FUSED selective scan (one channel per block) ---------------
// Phase 1: per-chunk (P, q) -> smem. Phase 2: serial h_in propagate in smem.
// Phase 3: local scan from h_in, y = (C.h + x*D)*silu(z), coalesced y writes.
__global__ void __launch_bounds__(256, 3)
k_scan(const float* __restrict__ Alog, const float* __restrict__ Dp_) {
    __shared__ float sP[NG * DS];     // [g][s]
    __shared__ float sq[NG * DS];
    __shared__ float shin[NG * DS];
    __shared__ float ybuf[16 * CHK];
    int ch = blockIdx.x;
    int b = ch >> 8, d = ch & 255;
    int u = threadIdx.x >> 4;         // chunk slot 0..15
    int s = threadIdx.x & 15;         // state
    float Aval = -__expf(Alog[d * DS + s]);
    float Dp = Dp_[d];
    const float* pdb = g_delta + (long)ch * LSEQ;
    const float* pxb = g_xc    + (long)ch * LSEQ;
    const float* pzb = g_zs    + (long)ch * LSEQ;
    const float* pBb = g_Bm    + (long)b * LSEQ * DS + s;
    const float* pCb = g_Cm    + (long)b * LSEQ * DS + s;

    // ---- phase 1: per-chunk P, q ----
    #pragma unroll
    for (int pass = 0; pass < 4; ++pass) {
        int g = pass * 16 + u;
        const float* pd = pdb + g * CHK;
        const float* px = pxb + g * CHK;
        const float* pB = pBb + (long)g * CHK * DS;
        float P = 1.f, q = 0.f;
        #pragma unroll 4
        for (int t = 0; t < CHK; t += 4) {
            float4 dv = *(const float4*)&pd[t];
            float4 xv = *(const float4*)&px[t];
            float B0 = pB[(t + 0) * DS], B1 = pB[(t + 1) * DS];
            float B2 = pB[(t + 2) * DS], B3 = pB[(t + 3) * DS];
            float a0 = __expf(dv.x * Aval); P *= a0; q = fmaf(a0, q, dv.x * xv.x * B0);
            float a1 = __expf(dv.y * Aval); P *= a1; q = fmaf(a1, q, dv.y * xv.y * B1);
            float a2 = __expf(dv.z * Aval); P *= a2; q = fmaf(a2, q, dv.z * xv.z * B2);
            float a3 = __expf(dv.w * Aval); P *= a3; q = fmaf(a3, q, dv.w * xv.w * B3);
        }
        sP[g * DS + s] = P;
        sq[g * DS + s] = q;
    }
    __syncthreads();
    // ---- phase 2: serial propagate (16 threads) ----
    if (threadIdx.x < 16) {
        int ss = threadIdx.x;
        float h = 0.f;
        #pragma unroll 8
        for (int g = 0; g < NG; ++g) {
            shin[g * DS + ss] = h;
            h = fmaf(sP[g * DS + ss], h, sq[g * DS + ss]);
        }
    }
    __syncthreads();
    // ---- phase 3: local scan from h_in ----
    #pragma unroll
    for (int pass = 0; pass < 4; ++pass) {
        int g = pass * 16 + u;
        const float* pd = pdb + g * CHK;
        const float* px = pxb + g * CHK;
        const float* pz = pzb + g * CHK;
        const float* pB = pBb + (long)g * CHK * DS;
        const float* pC = pCb + (long)g * CHK * DS;
        float h = shin[g * DS + s];
        #pragma unroll 2
        for (int t = 0; t < CHK; t += 4) {
            float4 dv = *(const float4*)&pd[t];
            float4 xv = *(const float4*)&px[t];
            float4 zv;
            if (s == 0) zv = *(const float4*)&pz[t];
            #pragma unroll
            for (int j = 0; j < 4; ++j) {
                float dvj = (j == 0) ? dv.x : (j == 1) ? dv.y : (j == 2) ? dv.z : dv.w;
                float xvj = (j == 0) ? xv.x : (j == 1) ? xv.y : (j == 2) ? xv.z : xv.w;
                float Bv = pB[(t + j) * DS];
                float Cv = pC[(t + j) * DS];
                float a = __expf(dvj * Aval);
                h = fmaf(a, h, dvj * xvj * Bv);
                float p = h * Cv;
                p += __shfl_xor_sync(0xffffffffu, p, 8);
                p += __shfl_xor_sync(0xffffffffu, p, 4);
                p += __shfl_xor_sync(0xffffffffu, p, 2);
                p += __shfl_xor_sync(0xffffffffu, p, 1);
                if (s == 0) {
                    float zvj = (j == 0) ? zv.x : (j == 1) ? zv.y : (j == 2) ? zv.z : zv.w;
                    ybuf[u * CHK + t + j] = (p + xvj * Dp) * zvj;
                }
            }
        }
        __syncthreads();
        float* py = g_y + (long)ch * LSEQ + pass * 1024;
        for (int i = threadIdx.x; i < 16 * CHK; i += 256) py[i] = ybuf[i];
        __syncthreads();
    }
}

// ---------------- K6: FUSED outproj + final --------------------------------------
__global__ void __launch_bounds__(256, 2)
k_outfin(const float* __restrict__ Wmo, const float* __restrict__ wn2,
         const float* __restrict__ Wwp, const float* __restrict__ bwp,
         const float* __restrict__ Wop, const float* __restrict__ bop,
         const float* __restrict__ x, float* __restrict__ out) {
    extern __shared__ float sm[];
    float* syT  = sm;               // 64*68 [k][permt(t)] y chunk ; later sxn [i][t]
    float* swT  = sm + 4352;        // 64*132 [k][o] Wmo chunk ; later stage/smm [t][132]
    float* swpT = sm + 12800;       // 8704: swpT [i][c] 64*132 ; later sopT [c][o] 128*68
    int tid = threadIdx.x;
    long t0 = (long)blockIdx.x * 64;
    int b = (int)(t0 >> 12);
    int lpos = (int)(t0 & (LSEQ - 1));
    int warp = tid >> 5, lane = tid & 31, g = lane >> 2, tg = lane & 3;
    int o0 = warp * 16;

    float c[8][4] = {};
    for (int kc = 0; kc < 4; ++kc) {
        __syncthreads();
        for (int idx = tid; idx < 64 * 16; idx += 256) {
            int t4 = idx & 15, k = idx >> 4;
            float4 v = *(const float4*)&g_y[(long)(b * DI + kc * 64 + k) * LSEQ + lpos + t4 * 4];
            int tb = t4 * 4;
            syT[k * 68 + permt(tb + 0)] = tf32f(v.x);
            syT[k * 68 + permt(tb + 1)] = tf32f(v.y);
            syT[k * 68 + permt(tb + 2)] = tf32f(v.z);
            syT[k * 68 + permt(tb + 3)] = tf32f(v.w);
        }
        for (int idx = tid; idx < 64 * DM; idx += 256) {
            int k = idx & 63, o = idx >> 6;
            swT[k * 132 + o] = tf32f(Wmo[(long)o * DI + kc * 64 + k]);
        }
        __syncthreads();
        #pragma unroll
        for (int ks = 0; ks < 8; ++ks) {
            int kk = ks * 8;
            uint32_t a0 = __float_as_uint(swT[(kk + tg) * 132 + o0 + g]);
            uint32_t a1 = __float_as_uint(swT[(kk + tg) * 132 + o0 + g + 8]);
            uint32_t a2 = __float_as_uint(swT[(kk + tg + 4) * 132 + o0 + g]);
            uint32_t a3 = __float_as_uint(swT[(kk + tg + 4) * 132 + o0 + g + 8]);
            float4 q00 = *(const float4*)&syT[(kk + tg) * 68 + g * 8];
            float4 q01 = *(const float4*)&syT[(kk + tg) * 68 + g * 8 + 4];
            float4 q10 = *(const float4*)&syT[(kk + tg + 4) * 68 + g * 8];
            float4 q11 = *(const float4*)&syT[(kk + tg + 4) * 68 + g * 8 + 4];
            MMA_TF32(c[0], a0, a1, a2, a3, __float_as_uint(q00.x), __float_as_uint(q10.x));
            MMA_TF32(c[1], a0, a1, a2, a3, __float_as_uint(q00.y), __float_as_uint(q10.y));
            MMA_TF32(c[2], a0, a1, a2, a3, __float_as_uint(q00.z), __float_as_uint(q10.z));
            MMA_TF32(c[3], a0, a1, a2, a3, __float_as_uint(q00.w), __float_as_uint(q10.w));
            MMA_TF32(c[4], a0, a1, a2, a3, __float_as_uint(q01.x), __float_as_uint(q11.x));
            MMA_TF32(c[5], a0, a1, a2, a3, __float_as_uint(q01.y), __float_as_uint(q11.y));
            MMA_TF32(c[6], a0, a1, a2, a3, __float_as_uint(q01.z), __float_as_uint(q11.z));
            MMA_TF32(c[7], a0, a1, a2, a3, __float_as_uint(q01.w), __float_as_uint(q11.w));
        }
    }
    __syncthreads();
    float* stage = swT;
    float* sxn   = syT;
    #pragma unroll
    for (int nt = 0; nt < 8; ++nt) {
        int t = nt * 8 + 2 * tg;
        stage[t * 132 + o0 + g]           = c[nt][0];
        stage[(t + 1) * 132 + o0 + g]     = c[nt][1];
        stage[t * 132 + o0 + g + 8]       = c[nt][2];
        stage[(t + 1) * 132 + o0 + g + 8] = c[nt][3];
    }
    for (int idx = tid; idx < 64 * 64; idx += 256) {
        int i = idx & 63, t = idx >> 6;
        sxn[i * 68 + t] = g_xn[(t0 + t) * DMO + i];
    }
    for (int idx = tid; idx < DM * DMO; idx += 256) {
        int i = idx & 63, cc = idx >> 6;
        swpT[i * 132 + cc] = Wwp[cc * DMO + i];
    }
    __syncthreads();
    {
        int t = tid >> 2, part = tid & 3;
        int ob = part * 32;
        float ss = 0.f;
        #pragma unroll
        for (int j = 0; j < 32; j += 4) {
            float4 v = *(const float4*)&stage[t * 132 + ob + j];
            ss = fmaf(v.x, v.x, fmaf(v.y, v.y, fmaf(v.z, v.z, fmaf(v.w, v.w, ss))));
        }
        ss += __shfl_xor_sync(0xffffffffu, ss, 1);
        ss += __shfl_xor_sync(0xffffffffu, ss, 2);
        float sc = rsqrtf(ss * (1.f / DM) + 1e-5f);
        long tt = t0 + t;
        #pragma unroll
        for (int j = 0; j < 32; j += 4) {
            float4 v  = *(const float4*)&stage[t * 132 + ob + j];
            float4 w2 = *(const float4*)&wn2[ob + j];
            float4 uq = *(const float4*)&g_u[tt * DM + ob + j];
            float4 ov = make_float4(v.x * sc * w2.x + uq.x, v.y * sc * w2.y + uq.y,
                                    v.z * sc * w2.z + uq.z, v.w * sc * w2.w + uq.w);
            *(float4*)&stage[t * 132 + ob + j] = ov;
        }
    }
    __syncthreads();
    int tx = tid & 31, ty = tid >> 5;
    float* smm = stage;
    {
        ull acc[4][4] = {};
        float4 w4 = *(const float4*)&swpT[tx << 2];
        ulonglong2 xa = *(const ulonglong2*)&sxn[ty * 8];
        ulonglong2 xb = *(const ulonglong2*)&sxn[ty * 8 + 4];
        #pragma unroll 8
        for (int i = 0; i < DMO; ++i) {
            ull wd0 = pk2(w4.x, w4.x), wd1 = pk2(w4.y, w4.y);
            ull wd2 = pk2(w4.z, w4.z), wd3 = pk2(w4.w, w4.w);
            ull x0 = xa.x, x1 = xa.y, x2 = xb.x, x3 = xb.y;
            w4 = *(const float4*)&swpT[(i + 1) * 132 + (tx << 2)];
            xa = *(const ulonglong2*)&sxn[(i + 1) * 68 + ty * 8];
            xb = *(const ulonglong2*)&sxn[(i + 1) * 68 + ty * 8 + 4];
            FMA16(acc, x0, x1, x2, x3, wd0, wd1, wd2, wd3);
        }
        float4 bq = *(const float4*)&bwp[tx << 2];
        float bj[4] = {bq.x, bq.y, bq.z, bq.w};
        #pragma unroll
        for (int p = 0; p < 4; ++p)
            #pragma unroll
            for (int j = 0; j < 4; ++j) {
                float2 v = upk(acc[p][j]);
                int cc = (tx << 2) + j;
                int ta = ty * 8 + 2 * p;
                float va = v.x + bj[j], vb = v.y + bj[j];
                float wa = va / (1.f + __expf(-va));
                float wb = vb / (1.f + __expf(-vb));
                smm[ta * 132 + cc] *= wa;
                smm[(ta + 1) * 132 + cc] *= wb;
            }
    }
    __syncthreads();
    float* sopT = swpT;
    for (int idx = tid; idx < DMO * DM; idx += 256) {
        int cc = idx & 127, o = idx >> 7;
        sopT[cc * 68 + o] = Wop[o * DM + cc];
    }
    __syncthreads();
    {
        int rowg = tid >> 4;
        int o4 = (tid & 15) << 2;
        float a2[4][4] = {};
        for (int cc = 0; cc < DM; cc += 4) {
            float4 q0 = *(const float4*)&sopT[(cc + 0) * 68 + o4];
            float4 q1 = *(const float4*)&sopT[(cc + 1) * 68 + o4];
            float4 q2 = *(const float4*)&sopT[(cc + 2) * 68 + o4];
            float4 q3 = *(const float4*)&sopT[(cc + 3) * 68 + o4];
            #pragma unroll
            for (int rr = 0; rr < 4; ++rr) {
                float4 pv = *(const float4*)&smm[(rowg * 4 + rr) * 132 + cc];
                a2[rr][0] = fmaf(pv.x, q0.x, fmaf(pv.y, q1.x, fmaf(pv.z, q2.x, fmaf(pv.w, q3.x, a2[rr][0]))));
                a2[rr][1] = fmaf(pv.x, q0.y, fmaf(pv.y, q1.y, fmaf(pv.z, q2.y, fmaf(pv.w, q3.y, a2[rr][1]))));
                a2[rr][2] = fmaf(pv.x, q0.z, fmaf(pv.y, q1.z, fmaf(pv.z, q2.z, fmaf(pv.w, q3.z, a2[rr][2]))));
                a2[rr][3] = fmaf(pv.x, q0.w, fmaf(pv.y, q1.w, fmaf(pv.z, q2.w, fmaf(pv.w, q3.w, a2[rr][3]))));
            }
        }
        float4 bq = *(const float4*)&bop[o4];
        #pragma unroll
        for (int rr = 0; rr < 4; ++rr) {
            long tg2 = t0 + rowg * 4 + rr;
            float4 xq = *(const float4*)&x[tg2 * DMO + o4];
            float4 ov = make_float4(a2[rr][0] + bq.x + xq.x, a2[rr][1] + bq.y + xq.y,
                                    a2[rr][2] + bq.z + xq.z, a2[rr][3] + bq.w + xq.w);
            *(float4*)&out[tg2 * DMO + o4] = ov;
        }
    }
}

// ---------------- launch -----------------------------------------------------------
extern "C" void kernel_launch(void* const* d_in, const int* in_sizes, int n_in,
                              void* d_out, int out_size) {
    const float* x    = (const float*)d_in[0];
    const float* wn1  = (const float*)d_in[1];
    const float* wn2  = (const float*)d_in[2];
    const float* Wip  = (const float*)d_in[3];
    const float* bip  = (const float*)d_in[4];
    const float* Wfp  = (const float*)d_in[5];
    const float* bfp  = (const float*)d_in[6];
    const float* Wwp  = (const float*)d_in[7];
    const float* bwp  = (const float*)d_in[8];
    const float* Wop  = (const float*)d_in[9];
    const float* bop  = (const float*)d_in[10];
    const float* Win  = (const float*)d_in[11];
    const float* cw   = (const float*)d_in[12];
    const float* cb   = (const float*)d_in[13];
    const float* Xp   = (const float*)d_in[14];
    const float* Wdt  = (const float*)d_in[15];
    const float* bdt  = (const float*)d_in[16];
    const float* Alog = (const float*)d_in[17];
    const float* Dpar = (const float*)d_in[18];
    const float* Wmo  = (const float*)d_in[19];
    float* out = (float*)d_out;

    const int SM_K1 = (64 * 68 + 65 * 132 + 64 + 16) * 4;
    const int SM_K2 = (12800 + 140 + 128 + 16) * 4;
    const int SM_K4 = (2560 + 256 * 65) * 4;
    const int SM_KOF = (4352 + 8448 + 8704) * 4;

    cudaFuncSetAttribute(k_rms_u,   cudaFuncAttributeMaxDynamicSharedMemorySize, SM_K1);
    cudaFuncSetAttribute(k_inproj,  cudaFuncAttributeMaxDynamicSharedMemorySize, SM_K2);
    cudaFuncSetAttribute(k_xproj,   cudaFuncAttributeMaxDynamicSharedMemorySize, SM_K4);
    cudaFuncSetAttribute(k_outfin,  cudaFuncAttributeMaxDynamicSharedMemorySize, SM_KOF);

    k_combine<<<32, 256>>>(Wfp, Wip, bip, bfp);
    k_combine2<<<128, 256>>>(Win);
    k_rms_u<<<TOK / 64, 256, SM_K1>>>(x, wn1);
    k_inproj<<<dim3(TOK / 64, 4), 256, SM_K2>>>(cw, cb);
    k_xproj<<<TOK / 64, 256, SM_K4>>>(Xp, Wdt, bdt);
    k_scan<<<NCH, 256>>>(Alog, Dpar);
    k_outfin<<<TOK / 64, 256, SM_KOF>>>(Wmo, wn2, Wwp, bwp, Wop, bop, x, out);
}

// round 15
// speedup vs baseline: 1.1440x; 1.0317x over previous
#include <cuda_runtime.h>
#include <cstdint>

#define TOK 16384
#define LSEQ 4096
#define NB 4
#define DMO 64      // input/output dim D
#define DM 128      // d_model of mamba (2D)
#define DI 256      // d_inner
#define DS 16       // d_state
#define DTR 8       // dt_rank
#define NCH 1024    // NB * DI channels
#define CHK 64      // chunk length
#define NG (LSEQ / CHK)   // 64 chunks

typedef unsigned long long ull;

__device__ __forceinline__ ull pk2(float a, float b) {
    ull r; asm("mov.b64 %0, {%1, %2};" : "=l"(r) : "f"(a), "f"(b)); return r;
}
__device__ __forceinline__ void fma2(ull& d, ull a, ull b) {
    asm("fma.rn.f32x2 %0, %1, %2, %3;" : "=l"(d) : "l"(a), "l"(b), "l"(d));
}
__device__ __forceinline__ float2 upk(ull v) {
    float2 r; asm("mov.b64 {%0, %1}, %2;" : "=f"(r.x), "=f"(r.y) : "l"(v)); return r;
}
__device__ __forceinline__ uint32_t tf32c(float f) {
    uint32_t r; asm("cvt.rna.tf32.f32 %0, %1;" : "=r"(r) : "f"(f)); return r;
}
__device__ __forceinline__ float tf32f(float f) {
    return __uint_as_float(tf32c(f));
}
__device__ __forceinline__ int permt(int t) { return ((t & 7) << 3) | (t >> 3); }

#define MMA_TF32(c, a0, a1, a2, a3, b0, b1) \
    asm volatile("mma.sync.aligned.m16n8k8.row.col.f32.tf32.tf32.f32 " \
        "{%0,%1,%2,%3}, {%4,%5,%6,%7}, {%8,%9}, {%0,%1,%2,%3};" \
        : "+f"((c)[0]), "+f"((c)[1]), "+f"((c)[2]), "+f"((c)[3]) \
        : "r"(a0), "r"(a1), "r"(a2), "r"(a3), "r"(b0), "r"(b1))

#define FMA16(acc, x0, x1, x2, x3, wd0, wd1, wd2, wd3) \
    fma2(acc[0][0], x0, wd0); fma2(acc[0][1], x0, wd1); fma2(acc[0][2], x0, wd2); fma2(acc[0][3], x0, wd3); \
    fma2(acc[1][0], x1, wd0); fma2(acc[1][1], x1, wd1); fma2(acc[1][2], x1, wd2); fma2(acc[1][3], x1, wd3); \
    fma2(acc[2][0], x2, wd0); fma2(acc[2][1], x2, wd1); fma2(acc[2][2], x2, wd2); fma2(acc[2][3], x2, wd3); \
    fma2(acc[3][0], x3, wd0); fma2(acc[3][1], x3, wd1); fma2(acc[3][2], x3, wd2); fma2(acc[3][3], x3, wd3)

// ---------------- scratch ----------------
// xc / zs / delta / y are CHANNEL-MAJOR: [(b*DI + d) * LSEQ + l]
__device__ float g_Wu[DM * DMO];      // W_fp @ W_ip
__device__ float g_bu[DM];            // W_fp @ b_ip + b_fp
__device__ float g_Wc[2 * DI * DMO];  // in_proj @ W_u   (512 x 64)
__device__ float g_bc[2 * DI];        // in_proj @ b_u
__device__ float g_xn[TOK * DMO];
__device__ float g_xc[NCH * LSEQ];
__device__ float g_zs[NCH * LSEQ];
__device__ float g_delta[NCH * LSEQ];
__device__ float g_Bm[TOK * DS];
__device__ float g_Cm[TOK * DS];
__device__ float g_y[NCH * LSEQ];

// ---------------- K0: compose W_u = W_fp @ W_ip, b_u = W_fp@b_ip + b_fp ----------
__global__ void k_combine(const float* __restrict__ Wfp, const float* __restrict__ Wip,
                          const float* __restrict__ bip, const float* __restrict__ bfp) {
    int idx = blockIdx.x * 256 + threadIdx.x;
    int o = idx / DMO, i = idx % DMO;
    float s = 0.f;
    for (int k = 0; k < DM; ++k) s = fmaf(Wfp[o * DM + k], Wip[k * DMO + i], s);
    g_Wu[idx] = s;
    if (blockIdx.x == 0 && threadIdx.x < DM) {
        int t = threadIdx.x;
        float sb = bfp[t];
        for (int k = 0; k < DM; ++k) sb = fmaf(Wfp[t * DM + k], bip[k], sb);
        g_bu[t] = sb;
    }
}

// ---------------- K0b: compose W_c = in_proj @ W_u, b_c = in_proj @ b_u ----------
__global__ void k_combine2(const float* __restrict__ Win) {
    int idx = blockIdx.x * 256 + threadIdx.x;
    int e = idx >> 6, i = idx & 63;
    float s = 0.f;
    for (int k = 0; k < DM; ++k) s = fmaf(Win[(long)e * DM + k], g_Wu[k * DMO + i], s);
    g_Wc[idx] = s;
    if (i == 0) {
        float sb = 0.f;
        for (int k = 0; k < DM; ++k) sb = fmaf(Win[(long)e * DM + k], g_bu[k], sb);
        g_bc[e] = sb;
    }
}

// ---------------- K1: rmsnorm1 only (u computed later inside k_outfin) ----------
__global__ void __launch_bounds__(256, 6)
k_rms(const float* __restrict__ x, const float* __restrict__ wn1) {
    __shared__ float sx[64 * 68];
    __shared__ float ssc[64];
    int tid = threadIdx.x;
    long t0 = (long)blockIdx.x * 64;
    for (int idx = tid; idx < 64 * 64; idx += 256) {
        int i = idx & 63, t = idx >> 6;
        sx[i * 68 + t] = x[(t0 + t) * DMO + i];
    }
    __syncthreads();
    if (tid < 64) {
        float ss = 0.f;
        for (int i = 0; i < DMO; ++i) { float v = sx[i * 68 + tid]; ss = fmaf(v, v, ss); }
        ssc[tid] = rsqrtf(ss * (1.f / DMO) + 1e-5f);
    }
    __syncthreads();
    for (int idx = tid; idx < 64 * 64; idx += 256) {
        int i = idx & 63, t = idx >> 6;
        g_xn[(t0 + t) * DMO + i] = sx[i * 68 + t] * ssc[t] * wn1[i];
    }
}

// ---------------- K2: xz = W_c @ xn + b_c (tf32 MMA, permuted B layout) ----------
__global__ void __launch_bounds__(256, 3)
k_inproj(const float* __restrict__ cw, const float* __restrict__ cb) {
    extern __shared__ float sm[];
    float* sxn   = sm;                 // [i][permt(t)] 64*68 tf32 ; cols 64-66 halo
    float* swT   = sm + 64 * 68;       // [i][e] 64*132 tf32
    float* sbc   = sm + 12800 + 140;   // 128 biases (persists, fp32)
    float* stage = sm;                 // [e][t'] 128*68 AFTER GEMM (reuse)
    int tid = threadIdx.x;
    long t0 = (long)blockIdx.x * 64;
    int e0 = blockIdx.y * 128;
    int b = (int)(t0 >> 12);
    int l0 = (int)(t0 & (LSEQ - 1));
    bool isx = (e0 < DI);

    for (int idx = tid; idx < 64 * 64; idx += 256) {
        int i = idx & 63, t = idx >> 6;
        sxn[i * 68 + permt(t)] = tf32f(g_xn[(t0 + t) * DMO + i]);
    }
    for (int idx = tid; idx < 128 * 64; idx += 256) {
        int i = idx & 63, e = idx >> 6;
        swT[i * 132 + e] = tf32f(g_Wc[(long)(e0 + e) * DMO + i]);
    }
    if (tid < 128) sbc[tid] = g_bc[e0 + tid];
    if (isx && tid < 192) {
        int i = tid & 63, j = tid >> 6;
        sxn[i * 68 + 64 + j] = (l0 > 0) ? tf32f(g_xn[(t0 - 3 + j) * DMO + i]) : 0.f;
    }
    __syncthreads();
    int warp = tid >> 5, lane = tid & 31, g = lane >> 2, tg = lane & 3;
    int ew = warp * 16;
    float c[8][4] = {};
    #pragma unroll
    for (int ks = 0; ks < 8; ++ks) {
        int kk = ks * 8;
        uint32_t a0 = __float_as_uint(swT[(kk + tg) * 132 + ew + g]);
        uint32_t a1 = __float_as_uint(swT[(kk + tg) * 132 + ew + g + 8]);
        uint32_t a2 = __float_as_uint(swT[(kk + tg + 4) * 132 + ew + g]);
        uint32_t a3 = __float_as_uint(swT[(kk + tg + 4) * 132 + ew + g + 8]);
        float4 q00 = *(const float4*)&sxn[(kk + tg) * 68 + g * 8];
        float4 q01 = *(const float4*)&sxn[(kk + tg) * 68 + g * 8 + 4];
        float4 q10 = *(const float4*)&sxn[(kk + tg + 4) * 68 + g * 8];
        float4 q11 = *(const float4*)&sxn[(kk + tg + 4) * 68 + g * 8 + 4];
        MMA_TF32(c[0], a0, a1, a2, a3, __float_as_uint(q00.x), __float_as_uint(q10.x));
        MMA_TF32(c[1], a0, a1, a2, a3, __float_as_uint(q00.y), __float_as_uint(q10.y));
        MMA_TF32(c[2], a0, a1, a2, a3, __float_as_uint(q00.z), __float_as_uint(q10.z));
        MMA_TF32(c[3], a0, a1, a2, a3, __float_as_uint(q00.w), __float_as_uint(q10.w));
        MMA_TF32(c[4], a0, a1, a2, a3, __float_as_uint(q01.x), __float_as_uint(q11.x));
        MMA_TF32(c[5], a0, a1, a2, a3, __float_as_uint(q01.y), __float_as_uint(q11.y));
        MMA_TF32(c[6], a0, a1, a2, a3, __float_as_uint(q01.z), __float_as_uint(q11.z));
        MMA_TF32(c[7], a0, a1, a2, a3, __float_as_uint(q01.w), __float_as_uint(q11.w));
    }
    float h1 = 0.f, h2 = 0.f;
    if (isx && l0 > 0) {
        {
            int j = tid >> 7, e = tid & 127;
            float a = sbc[e];
            for (int i = 0; i < 64; ++i)
                a = fmaf(sxn[i * 68 + 64 + j], swT[i * 132 + e], a);
            h1 = a;
        }
        if (tid < 128) {
            int e = tid;
            float a = sbc[e];
            for (int i = 0; i < 64; ++i)
                a = fmaf(sxn[i * 68 + 66], swT[i * 132 + e], a);
            h2 = a;
        }
    }
    __syncthreads();
    {
        float bc0 = sbc[ew + g], bc1 = sbc[ew + g + 8];
        #pragma unroll
        for (int nt = 0; nt < 8; ++nt) {
            int t = nt * 8 + 2 * tg;
            stage[(ew + g) * 68 + 3 + t]     = c[nt][0] + bc0;
            stage[(ew + g) * 68 + 4 + t]     = c[nt][1] + bc0;
            stage[(ew + g + 8) * 68 + 3 + t] = c[nt][2] + bc1;
            stage[(ew + g + 8) * 68 + 4 + t] = c[nt][3] + bc1;
        }
    }
    if (isx) {
        { int j = tid >> 7, e = tid & 127; stage[e * 68 + j] = h1; }
        if (tid < 128) stage[tid * 68 + 2] = h2;
    }
    __syncthreads();
    if (isx) {
        for (int idx = tid; idx < 128 * 64; idx += 256) {
            int t = idx & 63, e = idx >> 6;
            int d = e0 + e;
            const float* st = &stage[e * 68];
            float4 w = *(const float4*)&cw[d * 4];
            float a = cb[d];
            a = fmaf(w.x, st[t], a);
            a = fmaf(w.y, st[t + 1], a);
            a = fmaf(w.z, st[t + 2], a);
            a = fmaf(w.w, st[t + 3], a);
            a = a / (1.f + __expf(-a));
            g_xc[(long)(b * DI + d) * LSEQ + l0 + t] = a;
        }
    } else {
        for (int idx = tid; idx < 128 * 64; idx += 256) {
            int t = idx & 63, e = idx >> 6;
            float v = stage[e * 68 + 3 + t];
            v = v / (1.f + __expf(-v));
            g_zs[(long)(b * DI + (e0 - DI) + e) * LSEQ + l0 + t] = v;
        }
    }
}

// ---------------- K4: x_dbl = x_proj @ x ; B,C ; delta (K-chunked, smem reuse) ---
__global__ void __launch_bounds__(256, 2)
k_xproj(const float* __restrict__ Xp, const float* __restrict__ Wdt,
        const float* __restrict__ bdt) {
    extern __shared__ float sm[];
    float* sdbl = sm;                 // 64*40 (persists)
    float* sxc  = sm + 2560;          // phase1: [t][kk] 64*132
    float* spc  = sm + 2560 + 8448;   // phase1: [e][kk] 40*132
    float* sdel = sm + 2560;          // phase2: [d][t] 256*65
    int tid = threadIdx.x;
    long t0 = (long)blockIdx.x * 64;
    int b = (int)(t0 >> 12);
    int l0 = (int)(t0 & (LSEQ - 1));

    int tt = tid >> 2, eb = (tid & 3) * 10;
    float acc[10] = {};
    for (int kc = 0; kc < 2; ++kc) {
        __syncthreads();
        for (int idx = tid; idx < 64 * 128; idx += 256) {
            int t = idx & 63, kk = idx >> 6;
            sxc[t * 132 + kk] = g_xc[(long)(b * DI + kc * 128 + kk) * LSEQ + l0 + t];
        }
        for (int idx = tid; idx < 40 * 128; idx += 256) {
            int kk = idx & 127, e = idx >> 7;
            spc[e * 132 + kk] = Xp[e * DI + kc * 128 + kk];
        }
        __syncthreads();
        for (int kk = 0; kk < 128; kk += 4) {
            float4 xv = *(const float4*)&sxc[tt * 132 + kk];
            #pragma unroll
            for (int e = 0; e < 10; ++e) {
                float4 wv = *(const float4*)&spc[(eb + e) * 132 + kk];
                acc[e] = fmaf(xv.x, wv.x, fmaf(xv.y, wv.y, fmaf(xv.z, wv.z, fmaf(xv.w, wv.w, acc[e]))));
            }
        }
    }
    __syncthreads();
    #pragma unroll
    for (int e = 0; e < 10; ++e) sdbl[tt * 40 + eb + e] = acc[e];
    __syncthreads();
    for (int idx = tid; idx < 64 * DS; idx += 256) {
        int t = idx >> 4, s = idx & 15;
        g_Bm[(t0 + t) * DS + s] = sdbl[t * 40 + 8 + s];
        g_Cm[(t0 + t) * DS + s] = sdbl[t * 40 + 24 + s];
    }
    {
        int d = tid;
        float wr[8];
        #pragma unroll
        for (int r = 0; r < 8; ++r) wr[r] = Wdt[d * 8 + r];
        float bb = bdt[d];
        for (int t = 0; t < 64; ++t) {
            float pre = bb;
            #pragma unroll
            for (int r = 0; r < 8; ++r) pre = fmaf(sdbl[t * 40 + r], wr[r], pre);
            float sp = (pre > 20.f) ? pre : log1pf(__expf(pre));
            sdel[d * 65 + t] = sp;
        }
    }
    __syncthreads();
    for (int idx = tid; idx < DI * 64; idx += 256) {
        int d = idx >> 6, t = idx & 63;
        g_delta[(long)(b * DI + d) * LSEQ + l0 + t] = sdel[d * 65 + t];
    }
}

// ---------------- K5: FUSED selective scan (one channel per block) ---------------
__global__ void __launch_bounds__(256, 3)
k_scan(const float* __restrict__ Alog, const float* __restrict__ Dp_) {
    __shared__ float sP[NG * DS];
    __shared__ float sq[NG * DS];
    __shared__ float shin[NG * DS];
    __shared__ float ybuf[16 * CHK];
    int ch = blockIdx.x;
    int b = ch >> 8, d = ch & 255;
    int u = threadIdx.x >> 4;
    int s = threadIdx.x & 15;
    float Aval = -__expf(Alog[d * DS + s]);
    float Dp = Dp_[d];
    const float* pdb = g_delta + (long)ch * LSEQ;
    const float* pxb = g_xc    + (long)ch * LSEQ;
    const float* pzb = g_zs    + (long)ch * LSEQ;
    const float* pBb = g_Bm    + (long)b * LSEQ * DS + s;
    const float* pCb = g_Cm    + (long)b * LSEQ * DS + s;

    #pragma unroll
    for (int pass = 0; pass < 4; ++pass) {
        int g = pass * 16 + u;
        const float* pd = pdb + g * CHK;
        const float* px = pxb + g * CHK;
        const float* pB = pBb + (long)g * CHK * DS;
        float P = 1.f, q = 0.f;
        #pragma unroll 4
        for (int t = 0; t < CHK; t += 4) {
            float4 dv = *(const float4*)&pd[t];
            float4 xv = *(const float4*)&px[t];
            float B0 = pB[(t + 0) * DS], B1 = pB[(t + 1) * DS];
            float B2 = pB[(t + 2) * DS], B3 = pB[(t + 3) * DS];
            float a0 = __expf(dv.x * Aval); P *= a0; q = fmaf(a0, q, dv.x * xv.x * B0);
            float a1 = __expf(dv.y * Aval); P *= a1; q = fmaf(a1, q, dv.y * xv.y * B1);
            float a2 = __expf(dv.z * Aval); P *= a2; q = fmaf(a2, q, dv.z * xv.z * B2);
            float a3 = __expf(dv.w * Aval); P *= a3; q = fmaf(a3, q, dv.w * xv.w * B3);
        }
        sP[g * DS + s] = P;
        sq[g * DS + s] = q;
    }
    __syncthreads();
    if (threadIdx.x < 16) {
        int ss = threadIdx.x;
        float h = 0.f;
        #pragma unroll 8
        for (int g = 0; g < NG; ++g) {
            shin[g * DS + ss] = h;
            h = fmaf(sP[g * DS + ss], h, sq[g * DS + ss]);
        }
    }
    __syncthreads();
    #pragma unroll
    for (int pass = 0; pass < 4; ++pass) {
        int g = pass * 16 + u;
        const float* pd = pdb + g * CHK;
        const float* px = pxb + g * CHK;
        const float* pz = pzb + g * CHK;
        const float* pB = pBb + (long)g * CHK * DS;
        const float* pC = pCb + (long)g * CHK * DS;
        float h = shin[g * DS + s];
        #pragma unroll 2
        for (int t = 0; t < CHK; t += 4) {
            float4 dv = *(const float4*)&pd[t];
            float4 xv = *(const float4*)&px[t];
            float4 zv;
            if (s == 0) zv = *(const float4*)&pz[t];
            #pragma unroll
            for (int j = 0; j < 4; ++j) {
                float dvj = (j == 0) ? dv.x : (j == 1) ? dv.y : (j == 2) ? dv.z : dv.w;
                float xvj = (j == 0) ? xv.x : (j == 1) ? xv.y : (j == 2) ? xv.z : xv.w;
                float Bv = pB[(t + j) * DS];
                float Cv = pC[(t + j) * DS];
                float a = __expf(dvj * Aval);
                h = fmaf(a, h, dvj * xvj * Bv);
                float p = h * Cv;
                p += __shfl_xor_sync(0xffffffffu, p, 8);
                p += __shfl_xor_sync(0xffffffffu, p, 4);
                p += __shfl_xor_sync(0xffffffffu, p, 2);
                p += __shfl_xor_sync(0xffffffffu, p, 1);
                if (s == 0) {
                    float zvj = (j == 0) ? zv.x : (j == 1) ? zv.y : (j == 2) ? zv.z : zv.w;
                    ybuf[u * CHK + t + j] = (p + xvj * Dp) * zvj;
                }
            }
        }
        __syncthreads();
        float* py = g_y + (long)ch * LSEQ + pass * 1024;
        for (int i = threadIdx.x; i < 16 * CHK; i += 256) py[i] = ybuf[i];
        __syncthreads();
    }
}

// ---------------- K6: FUSED outproj + rmsnorm2(+u) + gating + final --------------
__global__ void __launch_bounds__(256, 2)
k_outfin(const float* __restrict__ Wmo, const float* __restrict__ wn2,
         const float* __restrict__ Wwp, const float* __restrict__ bwp,
         const float* __restrict__ Wop, const float* __restrict__ bop,
         const float* __restrict__ x, float* __restrict__ out) {
    extern __shared__ float sm[];
    float* syT  = sm;               // 64*68 [k][permt(t)] y chunk ; later sxn [i][t]
    float* swT  = sm + 4352;        // 64*132 [k][o] Wmo chunk ; later stage/smm [t][132]
    float* swpT = sm + 12800;       // 8704: Wu then Wwp [i][c] 64*132 ; later sopT 128*68
    float* ssc  = sm + 21504;       // 64 rmsnorm2 scales
    int tid = threadIdx.x;
    long t0 = (long)blockIdx.x * 64;
    int b = (int)(t0 >> 12);
    int lpos = (int)(t0 & (LSEQ - 1));
    int warp = tid >> 5, lane = tid & 31, g = lane >> 2, tg = lane & 3;
    int o0 = warp * 16;

    // -------- phase 1: mamba_out GEMM (tf32 MMA, K-chunked) --------
    float c[8][4] = {};
    for (int kc = 0; kc < 4; ++kc) {
        __syncthreads();
        for (int idx = tid; idx < 64 * 16; idx += 256) {
            int t4 = idx & 15, k = idx >> 4;
            float4 v = *(const float4*)&g_y[(long)(b * DI + kc * 64 + k) * LSEQ + lpos + t4 * 4];
            int tb = t4 * 4;
            syT[k * 68 + permt(tb + 0)] = tf32f(v.x);
            syT[k * 68 + permt(tb + 1)] = tf32f(v.y);
            syT[k * 68 + permt(tb + 2)] = tf32f(v.z);
            syT[k * 68 + permt(tb + 3)] = tf32f(v.w);
        }
        for (int idx = tid; idx < 64 * DM; idx += 256) {
            int k = idx & 63, o = idx >> 6;
            swT[k * 132 + o] = tf32f(Wmo[(long)o * DI + kc * 64 + k]);
        }
        __syncthreads();
        #pragma unroll
        for (int ks = 0; ks < 8; ++ks) {
            int kk = ks * 8;
            uint32_t a0 = __float_as_uint(swT[(kk + tg) * 132 + o0 + g]);
            uint32_t a1 = __float_as_uint(swT[(kk + tg) * 132 + o0 + g + 8]);
            uint32_t a2 = __float_as_uint(swT[(kk + tg + 4) * 132 + o0 + g]);
            uint32_t a3 = __float_as_uint(swT[(kk + tg + 4) * 132 + o0 + g + 8]);
            float4 q00 = *(const float4*)&syT[(kk + tg) * 68 + g * 8];
            float4 q01 = *(const float4*)&syT[(kk + tg) * 68 + g * 8 + 4];
            float4 q10 = *(const float4*)&syT[(kk + tg + 4) * 68 + g * 8];
            float4 q11 = *(const float4*)&syT[(kk + tg + 4) * 68 + g * 8 + 4];
            MMA_TF32(c[0], a0, a1, a2, a3, __float_as_uint(q00.x), __float_as_uint(q10.x));
            MMA_TF32(c[1], a0, a1, a2, a3, __float_as_uint(q00.y), __float_as_uint(q10.y));
            MMA_TF32(c[2], a0, a1, a2, a3, __float_as_uint(q00.z), __float_as_uint(q10.z));
            MMA_TF32(c[3], a0, a1, a2, a3, __float_as_uint(q00.w), __float_as_uint(q10.w));
            MMA_TF32(c[4], a0, a1, a2, a3, __float_as_uint(q01.x), __float_as_uint(q11.x));
            MMA_TF32(c[5], a0, a1, a2, a3, __float_as_uint(q01.y), __float_as_uint(q11.y));
            MMA_TF32(c[6], a0, a1, a2, a3, __float_as_uint(q01.z), __float_as_uint(q11.z));
            MMA_TF32(c[7], a0, a1, a2, a3, __float_as_uint(q01.w), __float_as_uint(q11.w));
        }
    }
    __syncthreads();
    float* stage = swT;     // [t][132] raw m
    float* sxn   = syT;     // [i][t] 64*68
    #pragma unroll
    for (int nt = 0; nt < 8; ++nt) {
        int t = nt * 8 + 2 * tg;
        stage[t * 132 + o0 + g]           = c[nt][0];
        stage[(t + 1) * 132 + o0 + g]     = c[nt][1];
        stage[t * 132 + o0 + g + 8]       = c[nt][2];
        stage[(t + 1) * 132 + o0 + g + 8] = c[nt][3];
    }
    for (int idx = tid; idx < 64 * 64; idx += 256) {
        int i = idx & 63, t = idx >> 6;
        sxn[i * 68 + t] = g_xn[(t0 + t) * DMO + i];
    }
    for (int idx = tid; idx < DM * DMO; idx += 256) {
        int i = idx & 63, cc = idx >> 6;
        swpT[i * 132 + cc] = g_Wu[cc * DMO + i];    // Wu first
    }
    __syncthreads();
    // -------- rmsnorm2 scales --------
    {
        int t = tid >> 2, part = tid & 3;
        int ob = part * 32;
        float ss = 0.f;
        #pragma unroll
        for (int j = 0; j < 32; j += 4) {
            float4 v = *(const float4*)&stage[t * 132 + ob + j];
            ss = fmaf(v.x, v.x, fmaf(v.y, v.y, fmaf(v.z, v.z, fmaf(v.w, v.w, ss))));
        }
        ss += __shfl_xor_sync(0xffffffffu, ss, 1);
        ss += __shfl_xor_sync(0xffffffffu, ss, 2);
        if (part == 0) ssc[t] = rsqrtf(ss * (1.f / DM) + 1e-5f);
    }
    __syncthreads();
    // -------- u-GEMM (f32x2) ; epilogue: stage = stage*sc*wn2 + u --------
    int tx = tid & 31, ty = tid >> 5;
    {
        ull acc[4][4] = {};
        float4 w4 = *(const float4*)&swpT[tx << 2];
        ulonglong2 xa = *(const ulonglong2*)&sxn[ty * 8];
        ulonglong2 xb = *(const ulonglong2*)&sxn[ty * 8 + 4];
        #pragma unroll 8
        for (int i = 0; i < DMO; ++i) {
            ull wd0 = pk2(w4.x, w4.x), wd1 = pk2(w4.y, w4.y);
            ull wd2 = pk2(w4.z, w4.z), wd3 = pk2(w4.w, w4.w);
            ull x0 = xa.x, x1 = xa.y, x2 = xb.x, x3 = xb.y;
            w4 = *(const float4*)&swpT[(i + 1) * 132 + (tx << 2)];
            xa = *(const ulonglong2*)&sxn[(i + 1) * 68 + ty * 8];
            xb = *(const ulonglong2*)&sxn[(i + 1) * 68 + ty * 8 + 4];
            FMA16(acc, x0, x1, x2, x3, wd0, wd1, wd2, wd3);
        }
        float4 bq = *(const float4*)&g_bu[tx << 2];
        float bj[4] = {bq.x, bq.y, bq.z, bq.w};
        float4 w2q = *(const float4*)&wn2[tx << 2];
        float wj[4] = {w2q.x, w2q.y, w2q.z, w2q.w};
        #pragma unroll
        for (int p = 0; p < 4; ++p) {
            int ta = ty * 8 + 2 * p;
            float sc0 = ssc[ta], sc1 = ssc[ta + 1];
            #pragma unroll
            for (int j = 0; j < 4; ++j) {
                float2 v = upk(acc[p][j]);
                int cc = (tx << 2) + j;
                float u0 = v.x + bj[j], u1 = v.y + bj[j];
                stage[ta * 132 + cc]       = stage[ta * 132 + cc]       * sc0 * wj[j] + u0;
                stage[(ta + 1) * 132 + cc] = stage[(ta + 1) * 132 + cc] * sc1 * wj[j] + u1;
            }
        }
    }
    __syncthreads();
    // -------- w-GEMM: w = swish(Wwp @ xn + bwp), gate m in place --------
    for (int idx = tid; idx < DM * DMO; idx += 256) {
        int i = idx & 63, cc = idx >> 6;
        swpT[i * 132 + cc] = Wwp[cc * DMO + i];
    }
    __syncthreads();
    float* smm = stage;
    {
        ull acc[4][4] = {};
        float4 w4 = *(const float4*)&swpT[tx << 2];
        ulonglong2 xa = *(const ulonglong2*)&sxn[ty * 8];
        ulonglong2 xb = *(const ulonglong2*)&sxn[ty * 8 + 4];
        #pragma unroll 8
        for (int i = 0; i < DMO; ++i) {
            ull wd0 = pk2(w4.x, w4.x), wd1 = pk2(w4.y, w4.y);
            ull wd2 = pk2(w4.z, w4.z), wd3 = pk2(w4.w, w4.w);
            ull x0 = xa.x, x1 = xa.y, x2 = xb.x, x3 = xb.y;
            w4 = *(const float4*)&swpT[(i + 1) * 132 + (tx << 2)];
            xa = *(const ulonglong2*)&sxn[(i + 1) * 68 + ty * 8];
            xb = *(const ulonglong2*)&sxn[(i + 1) * 68 + ty * 8 + 4];
            FMA16(acc, x0, x1, x2, x3, wd0, wd1, wd2, wd3);
        }
        float4 bq = *(const float4*)&bwp[tx << 2];
        float bj[4] = {bq.x, bq.y, bq.z, bq.w};
        #pragma unroll
        for (int p = 0; p < 4; ++p)
            #pragma unroll
            for (int j = 0; j < 4; ++j) {
                float2 v = upk(acc[p][j]);
                int cc = (tx << 2) + j;
                int ta = ty * 8 + 2 * p;
                float va = v.x + bj[j], vb = v.y + bj[j];
                float wa = va / (1.f + __expf(-va));
                float wb = vb / (1.f + __expf(-vb));
                smm[ta * 132 + cc] *= wa;
                smm[(ta + 1) * 132 + cc] *= wb;
            }
    }
    __syncthreads();
    float* sopT = swpT;
    for (int idx = tid; idx < DMO * DM; idx += 256) {
        int cc = idx & 127, o = idx >> 7;
        sopT[cc * 68 + o] = Wop[o * DM + cc];
    }
    __syncthreads();
    {
        int rowg = tid >> 4;
        int o4 = (tid & 15) << 2;
        float a2[4][4] = {};
        for (int cc = 0; cc < DM; cc += 4) {
            float4 q0 = *(const float4*)&sopT[(cc + 0) * 68 + o4];
            float4 q1 = *(const float4*)&sopT[(cc + 1) * 68 + o4];
            float4 q2 = *(const float4*)&sopT[(cc + 2) * 68 + o4];
            float4 q3 = *(const float4*)&sopT[(cc + 3) * 68 + o4];
            #pragma unroll
            for (int rr = 0; rr < 4; ++rr) {
                float4 pv = *(const float4*)&smm[(rowg * 4 + rr) * 132 + cc];
                a2[rr][0] = fmaf(pv.x, q0.x, fmaf(pv.y, q1.x, fmaf(pv.z, q2.x, fmaf(pv.w, q3.x, a2[rr][0]))));
                a2[rr][1] = fmaf(pv.x, q0.y, fmaf(pv.y, q1.y, fmaf(pv.z, q2.y, fmaf(pv.w, q3.y, a2[rr][1]))));
                a2[rr][2] = fmaf(pv.x, q0.z, fmaf(pv.y, q1.z, fmaf(pv.z, q2.z, fmaf(pv.w, q3.z, a2[rr][2]))));
                a2[rr][3] = fmaf(pv.x, q0.w, fmaf(pv.y, q1.w, fmaf(pv.z, q2.w, fmaf(pv.w, q3.w, a2[rr][3]))));
            }
        }
        float4 bq = *(const float4*)&bop[o4];
        #pragma unroll
        for (int rr = 0; rr < 4; ++rr) {
            long tg2 = t0 + rowg * 4 + rr;
            float4 xq = *(const float4*)&x[tg2 * DMO + o4];
            float4 ov = make_float4(a2[rr][0] + bq.x + xq.x, a2[rr][1] + bq.y + xq.y,
                                    a2[rr][2] + bq.z + xq.z, a2[rr][3] + bq.w + xq.w);
            *(float4*)&out[tg2 * DMO + o4] = ov;
        }
    }
}

// ---------------- launch -----------------------------------------------------------
extern "C" void kernel_launch(void* const* d_in, const int* in_sizes, int n_in,
                              void* d_out, int out_size) {
    const float* x    = (const float*)d_in[0];
    const float* wn1  = (const float*)d_in[1];
    const float* wn2  = (const float*)d_in[2];
    const float* Wip  = (const float*)d_in[3];
    const float* bip  = (const float*)d_in[4];
    const float* Wfp  = (const float*)d_in[5];
    const float* bfp  = (const float*)d_in[6];
    const float* Wwp  = (const float*)d_in[7];
    const float* bwp  = (const float*)d_in[8];
    const float* Wop  = (const float*)d_in[9];
    const float* bop  = (const float*)d_in[10];
    const float* Win  = (const float*)d_in[11];
    const float* cw   = (const float*)d_in[12];
    const float* cb   = (const float*)d_in[13];
    const float* Xp   = (const float*)d_in[14];
    const float* Wdt  = (const float*)d_in[15];
    const float* bdt  = (const float*)d_in[16];
    const float* Alog = (const float*)d_in[17];
    const float* Dpar = (const float*)d_in[18];
    const float* Wmo  = (const float*)d_in[19];
    float* out = (float*)d_out;

    const int SM_K2 = (12800 + 140 + 128 + 16) * 4;
    const int SM_K4 = (2560 + 256 * 65) * 4;
    const int SM_KOF = (21504 + 64 + 16) * 4;   // 86.3 KB -> 2 CTA/SM

    cudaFuncSetAttribute(k_inproj,  cudaFuncAttributeMaxDynamicSharedMemorySize, SM_K2);
    cudaFuncSetAttribute(k_xproj,   cudaFuncAttributeMaxDynamicSharedMemorySize, SM_K4);
    cudaFuncSetAttribute(k_outfin,  cudaFuncAttributeMaxDynamicSharedMemorySize, SM_KOF);

    k_combine<<<32, 256>>>(Wfp, Wip, bip, bfp);
    k_combine2<<<128, 256>>>(Win);
    k_rms<<<TOK / 64, 256>>>(x, wn1);
    k_inproj<<<dim3(TOK / 64, 4), 256, SM_K2>>>(cw, cb);
    k_xproj<<<TOK / 64, 256, SM_K4>>>(Xp, Wdt, bdt);
    k_scan<<<NCH, 256>>>(Alog, Dpar);
    k_outfin<<<TOK / 64, 256, SM_KOF>>>(Wmo, wn2, Wwp, bwp, Wop, bop, x, out);
}

// round 16
// speedup vs baseline: 1.1594x; 1.0134x over previous
#include <cuda_runtime.h>
#include <cstdint>

#define TOK 16384
#define LSEQ 4096
#define NB 4
#define DMO 64      // input/output dim D
#define DM 128      // d_model of mamba (2D)
#define DI 256      // d_inner
#define DS 16       // d_state
#define DTR 8       // dt_rank
#define NCH 1024    // NB * DI channels
#define CHK 64      // chunk length
#define NG (LSEQ / CHK)   // 64 chunks

typedef unsigned long long ull;

__device__ __forceinline__ ull pk2(float a, float b) {
    ull r; asm("mov.b64 %0, {%1, %2};" : "=l"(r) : "f"(a), "f"(b)); return r;
}
__device__ __forceinline__ void fma2(ull& d, ull a, ull b) {
    asm("fma.rn.f32x2 %0, %1, %2, %3;" : "=l"(d) : "l"(a), "l"(b), "l"(d));
}
__device__ __forceinline__ float2 upk(ull v) {
    float2 r; asm("mov.b64 {%0, %1}, %2;" : "=f"(r.x), "=f"(r.y) : "l"(v)); return r;
}
__device__ __forceinline__ uint32_t tf32c(float f) {
    uint32_t r; asm("cvt.rna.tf32.f32 %0, %1;" : "=r"(r) : "f"(f)); return r;
}
__device__ __forceinline__ float tf32f(float f) {
    return __uint_as_float(tf32c(f));
}
__device__ __forceinline__ int permt(int t) { return ((t & 7) << 3) | (t >> 3); }

#define MMA_TF32(c, a0, a1, a2, a3, b0, b1) \
    asm volatile("mma.sync.aligned.m16n8k8.row.col.f32.tf32.tf32.f32 " \
        "{%0,%1,%2,%3}, {%4,%5,%6,%7}, {%8,%9}, {%0,%1,%2,%3};" \
        : "+f"((c)[0]), "+f"((c)[1]), "+f"((c)[2]), "+f"((c)[3]) \
        : "r"(a0), "r"(a1), "r"(a2), "r"(a3), "r"(b0), "r"(b1))

#define FMA16(acc, x0, x1, x2, x3, wd0, wd1, wd2, wd3) \
    fma2(acc[0][0], x0, wd0); fma2(acc[0][1], x0, wd1); fma2(acc[0][2], x0, wd2); fma2(acc[0][3], x0, wd3); \
    fma2(acc[1][0], x1, wd0); fma2(acc[1][1], x1, wd1); fma2(acc[1][2], x1, wd2); fma2(acc[1][3], x1, wd3); \
    fma2(acc[2][0], x2, wd0); fma2(acc[2][1], x2, wd1); fma2(acc[2][2], x2, wd2); fma2(acc[2][3], x2, wd3); \
    fma2(acc[3][0], x3, wd0); fma2(acc[3][1], x3, wd1); fma2(acc[3][2], x3, wd2); fma2(acc[3][3], x3, wd3)

// ---------------- scratch ----------------
// xc / zs / delta / y are CHANNEL-MAJOR: [(b*DI + d) * LSEQ + l]
__device__ float g_Wu[DM * DMO];      // W_fp @ W_ip
__device__ float g_bu[DM];            // W_fp @ b_ip + b_fp
__device__ float g_Wc[2 * DI * DMO];  // in_proj @ W_u   (512 x 64)
__device__ float g_bc[2 * DI];        // in_proj @ b_u
__device__ float g_xc[NCH * LSEQ];
__device__ float g_zs[NCH * LSEQ];
__device__ float g_delta[NCH * LSEQ];
__device__ float g_Bm[TOK * DS];
__device__ float g_Cm[TOK * DS];
__device__ float g_y[NCH * LSEQ];

// ---------------- K0: compose W_u = W_fp @ W_ip, b_u = W_fp@b_ip + b_fp ----------
__global__ void k_combine(const float* __restrict__ Wfp, const float* __restrict__ Wip,
                          const float* __restrict__ bip, const float* __restrict__ bfp) {
    int idx = blockIdx.x * 256 + threadIdx.x;
    int o = idx / DMO, i = idx % DMO;
    float s = 0.f;
    for (int k = 0; k < DM; ++k) s = fmaf(Wfp[o * DM + k], Wip[k * DMO + i], s);
    g_Wu[idx] = s;
    if (blockIdx.x == 0 && threadIdx.x < DM) {
        int t = threadIdx.x;
        float sb = bfp[t];
        for (int k = 0; k < DM; ++k) sb = fmaf(Wfp[t * DM + k], bip[k], sb);
        g_bu[t] = sb;
    }
}

// ---------------- K0b: compose W_c = in_proj @ W_u, b_c = in_proj @ b_u ----------
__global__ void k_combine2(const float* __restrict__ Win) {
    int idx = blockIdx.x * 256 + threadIdx.x;
    int e = idx >> 6, i = idx & 63;
    float s = 0.f;
    for (int k = 0; k < DM; ++k) s = fmaf(Win[(long)e * DM + k], g_Wu[k * DMO + i], s);
    g_Wc[idx] = s;
    if (i == 0) {
        float sb = 0.f;
        for (int k = 0; k < DM; ++k) sb = fmaf(Win[(long)e * DM + k], g_bu[k], sb);
        g_bc[e] = sb;
    }
}

// ---------------- K2: rmsnorm1 in-block + xz = W_c @ xn + b_c (tf32 MMA) ---------
__global__ void __launch_bounds__(256, 3)
k_inproj(const float* __restrict__ x, const float* __restrict__ wn1,
         const float* __restrict__ cw, const float* __restrict__ cb) {
    extern __shared__ float sm[];
    float* sxn   = sm;                 // [i][permt(t)] 64*68 ; cols 64-66 halo
    float* swT   = sm + 64 * 68;       // [i][e] 64*132 tf32
    float* sbc   = sm + 12940;         // 128 biases (persists, fp32)
    float* ssc   = sm + 13068;         // 67+1 rmsnorm1 scales
    float* stage = sm;                 // [e][t'] 128*68 AFTER GEMM (reuse)
    int tid = threadIdx.x;
    long t0 = (long)blockIdx.x * 64;
    int e0 = blockIdx.y * 128;
    int b = (int)(t0 >> 12);
    int l0 = (int)(t0 & (LSEQ - 1));
    bool isx = (e0 < DI);

    for (int idx = tid; idx < 64 * 64; idx += 256) {
        int i = idx & 63, t = idx >> 6;
        sxn[i * 68 + permt(t)] = x[(t0 + t) * DMO + i];
    }
    for (int idx = tid; idx < 128 * 64; idx += 256) {
        int i = idx & 63, e = idx >> 6;
        swT[i * 132 + e] = tf32f(g_Wc[(long)(e0 + e) * DMO + i]);
    }
    if (tid < 128) sbc[tid] = g_bc[e0 + tid];
    if (isx && tid < 192) {   // halo x: tokens t0-3..t0-1
        int i = tid & 63, j = tid >> 6;
        sxn[i * 68 + 64 + j] = (l0 > 0) ? x[(t0 - 3 + j) * DMO + i] : 0.f;
    }
    __syncthreads();
    // rmsnorm1 scales per column (main 64 + halo 3)
    if (tid < 67) {
        float ss = 0.f;
        for (int i = 0; i < DMO; ++i) { float v = sxn[i * 68 + tid]; ss = fmaf(v, v, ss); }
        ssc[tid] = rsqrtf(ss * (1.f / DMO) + 1e-5f);
    }
    __syncthreads();
    for (int idx = tid; idx < 67 * 64; idx += 256) {
        int ct = idx >> 6, i = idx & 63;
        sxn[i * 68 + ct] = tf32f(sxn[i * 68 + ct] * ssc[ct] * wn1[i]);
    }
    __syncthreads();
    int warp = tid >> 5, lane = tid & 31, g = lane >> 2, tg = lane & 3;
    int ew = warp * 16;
    float c[8][4] = {};
    #pragma unroll
    for (int ks = 0; ks < 8; ++ks) {
        int kk = ks * 8;
        uint32_t a0 = __float_as_uint(swT[(kk + tg) * 132 + ew + g]);
        uint32_t a1 = __float_as_uint(swT[(kk + tg) * 132 + ew + g + 8]);
        uint32_t a2 = __float_as_uint(swT[(kk + tg + 4) * 132 + ew + g]);
        uint32_t a3 = __float_as_uint(swT[(kk + tg + 4) * 132 + ew + g + 8]);
        float4 q00 = *(const float4*)&sxn[(kk + tg) * 68 + g * 8];
        float4 q01 = *(const float4*)&sxn[(kk + tg) * 68 + g * 8 + 4];
        float4 q10 = *(const float4*)&sxn[(kk + tg + 4) * 68 + g * 8];
        float4 q11 = *(const float4*)&sxn[(kk + tg + 4) * 68 + g * 8 + 4];
        MMA_TF32(c[0], a0, a1, a2, a3, __float_as_uint(q00.x), __float_as_uint(q10.x));
        MMA_TF32(c[1], a0, a1, a2, a3, __float_as_uint(q00.y), __float_as_uint(q10.y));
        MMA_TF32(c[2], a0, a1, a2, a3, __float_as_uint(q00.z), __float_as_uint(q10.z));
        MMA_TF32(c[3], a0, a1, a2, a3, __float_as_uint(q00.w), __float_as_uint(q10.w));
        MMA_TF32(c[4], a0, a1, a2, a3, __float_as_uint(q01.x), __float_as_uint(q11.x));
        MMA_TF32(c[5], a0, a1, a2, a3, __float_as_uint(q01.y), __float_as_uint(q11.y));
        MMA_TF32(c[6], a0, a1, a2, a3, __float_as_uint(q01.z), __float_as_uint(q11.z));
        MMA_TF32(c[7], a0, a1, a2, a3, __float_as_uint(q01.w), __float_as_uint(q11.w));
    }
    float h1 = 0.f, h2 = 0.f;
    if (isx && l0 > 0) {
        {
            int j = tid >> 7, e = tid & 127;
            float a = sbc[e];
            for (int i = 0; i < 64; ++i)
                a = fmaf(sxn[i * 68 + 64 + j], swT[i * 132 + e], a);
            h1 = a;
        }
        if (tid < 128) {
            int e = tid;
            float a = sbc[e];
            for (int i = 0; i < 64; ++i)
                a = fmaf(sxn[i * 68 + 66], swT[i * 132 + e], a);
            h2 = a;
        }
    }
    __syncthreads();
    {
        float bc0 = sbc[ew + g], bc1 = sbc[ew + g + 8];
        #pragma unroll
        for (int nt = 0; nt < 8; ++nt) {
            int t = nt * 8 + 2 * tg;
            stage[(ew + g) * 68 + 3 + t]     = c[nt][0] + bc0;
            stage[(ew + g) * 68 + 4 + t]     = c[nt][1] + bc0;
            stage[(ew + g + 8) * 68 + 3 + t] = c[nt][2] + bc1;
            stage[(ew + g + 8) * 68 + 4 + t] = c[nt][3] + bc1;
        }
    }
    if (isx) {
        { int j = tid >> 7, e = tid & 127; stage[e * 68 + j] = h1; }
        if (tid < 128) stage[tid * 68 + 2] = h2;
    }
    __syncthreads();
    if (isx) {
        for (int idx = tid; idx < 128 * 64; idx += 256) {
            int t = idx & 63, e = idx >> 6;
            int d = e0 + e;
            const float* st = &stage[e * 68];
            float4 w = *(const float4*)&cw[d * 4];
            float a = cb[d];
            a = fmaf(w.x, st[t], a);
            a = fmaf(w.y, st[t + 1], a);
            a = fmaf(w.z, st[t + 2], a);
            a = fmaf(w.w, st[t + 3], a);
            a = a / (1.f + __expf(-a));
            g_xc[(long)(b * DI + d) * LSEQ + l0 + t] = a;
        }
    } else {
        for (int idx = tid; idx < 128 * 64; idx += 256) {
            int t = idx & 63, e = idx >> 6;
            float v = stage[e * 68 + 3 + t];
            v = v / (1.f + __expf(-v));
            g_zs[(long)(b * DI + (e0 - DI) + e) * LSEQ + l0 + t] = v;
        }
    }
}

// ---------------- K4: x_dbl = x_proj @ x ; B,C ; delta (K-chunked, smem reuse) ---
__global__ void __launch_bounds__(256, 2)
k_xproj(const float* __restrict__ Xp, const float* __restrict__ Wdt,
        const float* __restrict__ bdt) {
    extern __shared__ float sm[];
    float* sdbl = sm;                 // 64*40 (persists)
    float* sxc  = sm + 2560;          // phase1: [t][kk] 64*132
    float* spc  = sm + 2560 + 8448;   // phase1: [e][kk] 40*132
    float* sdel = sm + 2560;          // phase2: [d][t] 256*65
    int tid = threadIdx.x;
    long t0 = (long)blockIdx.x * 64;
    int b = (int)(t0 >> 12);
    int l0 = (int)(t0 & (LSEQ - 1));

    int tt = tid >> 2, eb = (tid & 3) * 10;
    float acc[10] = {};
    for (int kc = 0; kc < 2; ++kc) {
        __syncthreads();
        for (int idx = tid; idx < 64 * 128; idx += 256) {
            int t = idx & 63, kk = idx >> 6;
            sxc[t * 132 + kk] = g_xc[(long)(b * DI + kc * 128 + kk) * LSEQ + l0 + t];
        }
        for (int idx = tid; idx < 40 * 128; idx += 256) {
            int kk = idx & 127, e = idx >> 7;
            spc[e * 132 + kk] = Xp[e * DI + kc * 128 + kk];
        }
        __syncthreads();
        for (int kk = 0; kk < 128; kk += 4) {
            float4 xv = *(const float4*)&sxc[tt * 132 + kk];
            #pragma unroll
            for (int e = 0; e < 10; ++e) {
                float4 wv = *(const float4*)&spc[(eb + e) * 132 + kk];
                acc[e] = fmaf(xv.x, wv.x, fmaf(xv.y, wv.y, fmaf(xv.z, wv.z, fmaf(xv.w, wv.w, acc[e]))));
            }
        }
    }
    __syncthreads();
    #pragma unroll
    for (int e = 0; e < 10; ++e) sdbl[tt * 40 + eb + e] = acc[e];
    __syncthreads();
    for (int idx = tid; idx < 64 * DS; idx += 256) {
        int t = idx >> 4, s = idx & 15;
        g_Bm[(t0 + t) * DS + s] = sdbl[t * 40 + 8 + s];
        g_Cm[(t0 + t) * DS + s] = sdbl[t * 40 + 24 + s];
    }
    {
        int d = tid;
        float wr[8];
        #pragma unroll
        for (int r = 0; r < 8; ++r) wr[r] = Wdt[d * 8 + r];
        float bb = bdt[d];
        for (int t = 0; t < 64; ++t) {
            float pre = bb;
            #pragma unroll
            for (int r = 0; r < 8; ++r) pre = fmaf(sdbl[t * 40 + r], wr[r], pre);
            float sp = (pre > 20.f) ? pre : log1pf(__expf(pre));
            sdel[d * 65 + t] = sp;
        }
    }
    __syncthreads();
    for (int idx = tid; idx < DI * 64; idx += 256) {
        int d = idx >> 6, t = idx & 63;
        g_delta[(long)(b * DI + d) * LSEQ + l0 + t] = sdel[d * 65 + t];
    }
}

// ---------------- K5: FUSED selective scan (one channel per block) ---------------
__global__ void __launch_bounds__(256, 3)
k_scan(const float* __restrict__ Alog, const float* __restrict__ Dp_) {
    __shared__ float sP[NG * DS];
    __shared__ float sq[NG * DS];
    __shared__ float shin[NG * DS];
    __shared__ float ybuf[16 * CHK];
    int ch = blockIdx.x;
    int b = ch >> 8, d = ch & 255;
    int u = threadIdx.x >> 4;
    int s = threadIdx.x & 15;
    float Aval = -__expf(Alog[d * DS + s]);
    float Dp = Dp_[d];
    const float* pdb = g_delta + (long)ch * LSEQ;
    const float* pxb = g_xc    + (long)ch * LSEQ;
    const float* pzb = g_zs    + (long)ch * LSEQ;
    const float* pBb = g_Bm    + (long)b * LSEQ * DS + s;
    const float* pCb = g_Cm    + (long)b * LSEQ * DS + s;

    #pragma unroll
    for (int pass = 0; pass < 4; ++pass) {
        int g = pass * 16 + u;
        const float* pd = pdb + g * CHK;
        const float* px = pxb + g * CHK;
        const float* pB = pBb + (long)g * CHK * DS;
        float P = 1.f, q = 0.f;
        #pragma unroll 4
        for (int t = 0; t < CHK; t += 4) {
            float4 dv = *(const float4*)&pd[t];
            float4 xv = *(const float4*)&px[t];
            float B0 = pB[(t + 0) * DS], B1 = pB[(t + 1) * DS];
            float B2 = pB[(t + 2) * DS], B3 = pB[(t + 3) * DS];
            float a0 = __expf(dv.x * Aval); P *= a0; q = fmaf(a0, q, dv.x * xv.x * B0);
            float a1 = __expf(dv.y * Aval); P *= a1; q = fmaf(a1, q, dv.y * xv.y * B1);
            float a2 = __expf(dv.z * Aval); P *= a2; q = fmaf(a2, q, dv.z * xv.z * B2);
            float a3 = __expf(dv.w * Aval); P *= a3; q = fmaf(a3, q, dv.w * xv.w * B3);
        }
        sP[g * DS + s] = P;
        sq[g * DS + s] = q;
    }
    __syncthreads();
    if (threadIdx.x < 16) {
        int ss = threadIdx.x;
        float h = 0.f;
        #pragma unroll 8
        for (int g = 0; g < NG; ++g) {
            shin[g * DS + ss] = h;
            h = fmaf(sP[g * DS + ss], h, sq[g * DS + ss]);
        }
    }
    __syncthreads();
    #pragma unroll
    for (int pass = 0; pass < 4; ++pass) {
        int g = pass * 16 + u;
        const float* pd = pdb + g * CHK;
        const float* px = pxb + g * CHK;
        const float* pz = pzb + g * CHK;
        const float* pB = pBb + (long)g * CHK * DS;
        const float* pC = pCb + (long)g * CHK * DS;
        float h = shin[g * DS + s];
        #pragma unroll 2
        for (int t = 0; t < CHK; t += 4) {
            float4 dv = *(const float4*)&pd[t];
            float4 xv = *(const float4*)&px[t];
            float4 zv;
            if (s == 0) zv = *(const float4*)&pz[t];
            #pragma unroll
            for (int j = 0; j < 4; ++j) {
                float dvj = (j == 0) ? dv.x : (j == 1) ? dv.y : (j == 2) ? dv.z : dv.w;
                float xvj = (j == 0) ? xv.x : (j == 1) ? xv.y : (j == 2) ? xv.z : xv.w;
                float Bv = pB[(t + j) * DS];
                float Cv = pC[(t + j) * DS];
                float a = __expf(dvj * Aval);
                h = fmaf(a, h, dvj * xvj * Bv);
                float p = h * Cv;
                p += __shfl_xor_sync(0xffffffffu, p, 8);
                p += __shfl_xor_sync(0xffffffffu, p, 4);
                p += __shfl_xor_sync(0xffffffffu, p, 2);
                p += __shfl_xor_sync(0xffffffffu, p, 1);
                if (s == 0) {
                    float zvj = (j == 0) ? zv.x : (j == 1) ? zv.y : (j == 2) ? zv.z : zv.w;
                    ybuf[u * CHK + t + j] = (p + xvj * Dp) * zvj;
                }
            }
        }
        __syncthreads();
        float* py = g_y + (long)ch * LSEQ + pass * 1024;
        for (int i = threadIdx.x; i < 16 * CHK; i += 256) py[i] = ybuf[i];
        __syncthreads();
    }
}

// ---------------- K6: FUSED outproj + rmsnorm1/2 + u + gating + final ------------
__global__ void __launch_bounds__(256, 2)
k_outfin(const float* __restrict__ Wmo, const float* __restrict__ wn2,
         const float* __restrict__ wn1,
         const float* __restrict__ Wwp, const float* __restrict__ bwp,
         const float* __restrict__ Wop, const float* __restrict__ bop,
         const float* __restrict__ x, float* __restrict__ out) {
    extern __shared__ float sm[];
    float* syT  = sm;               // 64*68 [k][permt(t)] y chunk ; later sxn [i][t]
    float* swT  = sm + 4352;        // 64*132 [k][o] Wmo chunk ; later stage/smm [t][132]
    float* swpT = sm + 12800;       // 8704: Wu then Wwp [i][c] 64*132 ; later sopT 128*68
    float* ssc  = sm + 21504;       // 64 rmsnorm2 scales
    float* sxsc = sm + 21568;       // 64 rmsnorm1 scales
    int tid = threadIdx.x;
    long t0 = (long)blockIdx.x * 64;
    int b = (int)(t0 >> 12);
    int lpos = (int)(t0 & (LSEQ - 1));
    int warp = tid >> 5, lane = tid & 31, g = lane >> 2, tg = lane & 3;
    int o0 = warp * 16;

    // -------- phase 1: mamba_out GEMM (tf32 MMA, K-chunked) --------
    float c[8][4] = {};
    for (int kc = 0; kc < 4; ++kc) {
        __syncthreads();
        for (int idx = tid; idx < 64 * 16; idx += 256) {
            int t4 = idx & 15, k = idx >> 4;
            float4 v = *(const float4*)&g_y[(long)(b * DI + kc * 64 + k) * LSEQ + lpos + t4 * 4];
            int tb = t4 * 4;
            syT[k * 68 + permt(tb + 0)] = tf32f(v.x);
            syT[k * 68 + permt(tb + 1)] = tf32f(v.y);
            syT[k * 68 + permt(tb + 2)] = tf32f(v.z);
            syT[k * 68 + permt(tb + 3)] = tf32f(v.w);
        }
        for (int idx = tid; idx < 64 * DM; idx += 256) {
            int k = idx & 63, o = idx >> 6;
            swT[k * 132 + o] = tf32f(Wmo[(long)o * DI + kc * 64 + k]);
        }
        __syncthreads();
        #pragma unroll
        for (int ks = 0; ks < 8; ++ks) {
            int kk = ks * 8;
            uint32_t a0 = __float_as_uint(swT[(kk + tg) * 132 + o0 + g]);
            uint32_t a1 = __float_as_uint(swT[(kk + tg) * 132 + o0 + g + 8]);
            uint32_t a2 = __float_as_uint(swT[(kk + tg + 4) * 132 + o0 + g]);
            uint32_t a3 = __float_as_uint(swT[(kk + tg + 4) * 132 + o0 + g + 8]);
            float4 q00 = *(const float4*)&syT[(kk + tg) * 68 + g * 8];
            float4 q01 = *(const float4*)&syT[(kk + tg) * 68 + g * 8 + 4];
            float4 q10 = *(const float4*)&syT[(kk + tg + 4) * 68 + g * 8];
            float4 q11 = *(const float4*)&syT[(kk + tg + 4) * 68 + g * 8 + 4];
            MMA_TF32(c[0], a0, a1, a2, a3, __float_as_uint(q00.x), __float_as_uint(q10.x));
            MMA_TF32(c[1], a0, a1, a2, a3, __float_as_uint(q00.y), __float_as_uint(q10.y));
            MMA_TF32(c[2], a0, a1, a2, a3, __float_as_uint(q00.z), __float_as_uint(q10.z));
            MMA_TF32(c[3], a0, a1, a2, a3, __float_as_uint(q00.w), __float_as_uint(q10.w));
            MMA_TF32(c[4], a0, a1, a2, a3, __float_as_uint(q01.x), __float_as_uint(q11.x));
            MMA_TF32(c[5], a0, a1, a2, a3, __float_as_uint(q01.y), __float_as_uint(q11.y));
            MMA_TF32(c[6], a0, a1, a2, a3, __float_as_uint(q01.z), __float_as_uint(q11.z));
            MMA_TF32(c[7], a0, a1, a2, a3, __float_as_uint(q01.w), __float_as_uint(q11.w));
        }
    }
    __syncthreads();
    float* stage = swT;     // [t][132] raw m
    float* sxn   = syT;     // [i][t] 64*68
    #pragma unroll
    for (int nt = 0; nt < 8; ++nt) {
        int t = nt * 8 + 2 * tg;
        stage[t * 132 + o0 + g]           = c[nt][0];
        stage[(t + 1) * 132 + o0 + g]     = c[nt][1];
        stage[t * 132 + o0 + g + 8]       = c[nt][2];
        stage[(t + 1) * 132 + o0 + g + 8] = c[nt][3];
    }
    for (int idx = tid; idx < 64 * 64; idx += 256) {
        int i = idx & 63, t = idx >> 6;
        sxn[i * 68 + t] = x[(t0 + t) * DMO + i];     // raw x
    }
    for (int idx = tid; idx < DM * DMO; idx += 256) {
        int i = idx & 63, cc = idx >> 6;
        swpT[i * 132 + cc] = g_Wu[cc * DMO + i];    // Wu first
    }
    __syncthreads();
    // -------- rmsnorm2 scales + rmsnorm1 scales --------
    {
        int t = tid >> 2, part = tid & 3;
        int ob = part * 32;
        float ss = 0.f;
        #pragma unroll
        for (int j = 0; j < 32; j += 4) {
            float4 v = *(const float4*)&stage[t * 132 + ob + j];
            ss = fmaf(v.x, v.x, fmaf(v.y, v.y, fmaf(v.z, v.z, fmaf(v.w, v.w, ss))));
        }
        ss += __shfl_xor_sync(0xffffffffu, ss, 1);
        ss += __shfl_xor_sync(0xffffffffu, ss, 2);
        if (part == 0) ssc[t] = rsqrtf(ss * (1.f / DM) + 1e-5f);
    }
    if (tid < 64) {
        float ss = 0.f;
        for (int i = 0; i < DMO; ++i) { float v = sxn[i * 68 + tid]; ss = fmaf(v, v, ss); }
        sxsc[tid] = rsqrtf(ss * (1.f / DMO) + 1e-5f);
    }
    __syncthreads();
    for (int idx = tid; idx < 64 * 64; idx += 256) {
        int i = idx & 63, t = idx >> 6;
        sxn[i * 68 + t] = sxn[i * 68 + t] * sxsc[t] * wn1[i];
    }
    __syncthreads();
    // -------- u-GEMM (f32x2) ; epilogue: stage = stage*sc*wn2 + u --------
    int tx = tid & 31, ty = tid >> 5;
    {
        ull acc[4][4] = {};
        float4 w4 = *(const float4*)&swpT[tx << 2];
        ulonglong2 xa = *(const ulonglong2*)&sxn[ty * 8];
        ulonglong2 xb = *(const ulonglong2*)&sxn[ty * 8 + 4];
        #pragma unroll 8
        for (int i = 0; i < DMO; ++i) {
            ull wd0 = pk2(w4.x, w4.x), wd1 = pk2(w4.y, w4.y);
            ull wd2 = pk2(w4.z, w4.z), wd3 = pk2(w4.w, w4.w);
            ull x0 = xa.x, x1 = xa.y, x2 = xb.x, x3 = xb.y;
            w4 = *(const float4*)&swpT[(i + 1) * 132 + (tx << 2)];
            xa = *(const ulonglong2*)&sxn[(i + 1) * 68 + ty * 8];
            xb = *(const ulonglong2*)&sxn[(i + 1) * 68 + ty * 8 + 4];
            FMA16(acc, x0, x1, x2, x3, wd0, wd1, wd2, wd3);
        }
        float4 bq = *(const float4*)&g_bu[tx << 2];
        float bj[4] = {bq.x, bq.y, bq.z, bq.w};
        float4 w2q = *(const float4*)&wn2[tx << 2];
        float wj[4] = {w2q.x, w2q.y, w2q.z, w2q.w};
        #pragma unroll
        for (int p = 0; p < 4; ++p) {
            int ta = ty * 8 + 2 * p;
            float sc0 = ssc[ta], sc1 = ssc[ta + 1];
            #pragma unroll
            for (int j = 0; j < 4; ++j) {
                float2 v = upk(acc[p][j]);
                int cc = (tx << 2) + j;
                float u0 = v.x + bj[j], u1 = v.y + bj[j];
                stage[ta * 132 + cc]       = stage[ta * 132 + cc]       * sc0 * wj[j] + u0;
                stage[(ta + 1) * 132 + cc] = stage[(ta + 1) * 132 + cc] * sc1 * wj[j] + u1;
            }
        }
    }
    __syncthreads();
    // -------- w-GEMM: w = swish(Wwp @ xn + bwp), gate m in place --------
    for (int idx = tid; idx < DM * DMO; idx += 256) {
        int i = idx & 63, cc = idx >> 6;
        swpT[i * 132 + cc] = Wwp[cc * DMO + i];
    }
    __syncthreads();
    float* smm = stage;
    {
        ull acc[4][4] = {};
        float4 w4 = *(const float4*)&swpT[tx << 2];
        ulonglong2 xa = *(const ulonglong2*)&sxn[ty * 8];
        ulonglong2 xb = *(const ulonglong2*)&sxn[ty * 8 + 4];
        #pragma unroll 8
        for (int i = 0; i < DMO; ++i) {
            ull wd0 = pk2(w4.x, w4.x), wd1 = pk2(w4.y, w4.y);
            ull wd2 = pk2(w4.z, w4.z), wd3 = pk2(w4.w, w4.w);
            ull x0 = xa.x, x1 = xa.y, x2 = xb.x, x3 = xb.y;
            w4 = *(const float4*)&swpT[(i + 1) * 132 + (tx << 2)];
            xa = *(const ulonglong2*)&sxn[(i + 1) * 68 + ty * 8];
            xb = *(const ulonglong2*)&sxn[(i + 1) * 68 + ty * 8 + 4];
            FMA16(acc, x0, x1, x2, x3, wd0, wd1, wd2, wd3);
        }
        float4 bq = *(const float4*)&bwp[tx << 2];
        float bj[4] = {bq.x, bq.y, bq.z, bq.w};
        #pragma unroll
        for (int p = 0; p < 4; ++p)
            #pragma unroll
            for (int j = 0; j < 4; ++j) {
                float2 v = upk(acc[p][j]);
                int cc = (tx << 2) + j;
                int ta = ty * 8 + 2 * p;
                float va = v.x + bj[j], vb = v.y + bj[j];
                float wa = va / (1.f + __expf(-va));
                float wb = vb / (1.f + __expf(-vb));
                smm[ta * 132 + cc] *= wa;
                smm[(ta + 1) * 132 + cc] *= wb;
            }
    }
    __syncthreads();
    float* sopT = swpT;
    for (int idx = tid; idx < DMO * DM; idx += 256) {
        int cc = idx & 127, o = idx >> 7;
        sopT[cc * 68 + o] = Wop[o * DM + cc];
    }
    __syncthreads();
    {
        int rowg = tid >> 4;
        int o4 = (tid & 15) << 2;
        float a2[4][4] = {};
        for (int cc = 0; cc < DM; cc += 4) {
            float4 q0 = *(const float4*)&sopT[(cc + 0) * 68 + o4];
            float4 q1 = *(const float4*)&sopT[(cc + 1) * 68 + o4];
            float4 q2 = *(const float4*)&sopT[(cc + 2) * 68 + o4];
            float4 q3 = *(const float4*)&sopT[(cc + 3) * 68 + o4];
            #pragma unroll
            for (int rr = 0; rr < 4; ++rr) {
                float4 pv = *(const float4*)&smm[(rowg * 4 + rr) * 132 + cc];
                a2[rr][0] = fmaf(pv.x, q0.x, fmaf(pv.y, q1.x, fmaf(pv.z, q2.x, fmaf(pv.w, q3.x, a2[rr][0]))));
                a2[rr][1] = fmaf(pv.x, q0.y, fmaf(pv.y, q1.y, fmaf(pv.z, q2.y, fmaf(pv.w, q3.y, a2[rr][1]))));
                a2[rr][2] = fmaf(pv.x, q0.z, fmaf(pv.y, q1.z, fmaf(pv.z, q2.z, fmaf(pv.w, q3.z, a2[rr][2]))));
                a2[rr][3] = fmaf(pv.x, q0.w, fmaf(pv.y, q1.w, fmaf(pv.z, q2.w, fmaf(pv.w, q3.w, a2[rr][3]))));
            }
        }
        float4 bq = *(const float4*)&bop[o4];
        #pragma unroll
        for (int rr = 0; rr < 4; ++rr) {
            long tg2 = t0 + rowg * 4 + rr;
            float4 xq = *(const float4*)&x[tg2 * DMO + o4];
            float4 ov = make_float4(a2[rr][0] + bq.x + xq.x, a2[rr][1] + bq.y + xq.y,
                                    a2[rr][2] + bq.z + xq.z, a2[rr][3] + bq.w + xq.w);
            *(float4*)&out[tg2 * DMO + o4] = ov;
        }
    }
}

// ---------------- launch -----------------------------------------------------------
extern "C" void kernel_launch(void* const* d_in, const int* in_sizes, int n_in,
                              void* d_out, int out_size) {
    const float* x    = (const float*)d_in[0];
    const float* wn1  = (const float*)d_in[1];
    const float* wn2  = (const float*)d_in[2];
    const float* Wip  = (const float*)d_in[3];
    const float* bip  = (const float*)d_in[4];
    const float* Wfp  = (const float*)d_in[5];
    const float* bfp  = (const float*)d_in[6];
    const float* Wwp  = (const float*)d_in[7];
    const float* bwp  = (const float*)d_in[8];
    const float* Wop  = (const float*)d_in[9];
    const float* bop  = (const float*)d_in[10];
    const float* Win  = (const float*)d_in[11];
    const float* cw   = (const float*)d_in[12];
    const float* cb   = (const float*)d_in[13];
    const float* Xp   = (const float*)d_in[14];
    const float* Wdt  = (const float*)d_in[15];
    const float* bdt  = (const float*)d_in[16];
    const float* Alog = (const float*)d_in[17];
    const float* Dpar = (const float*)d_in[18];
    const float* Wmo  = (const float*)d_in[19];
    float* out = (float*)d_out;

    const int SM_K2 = (13068 + 68 + 16) * 4;       // ~52.6 KB -> 3 CTA/SM
    const int SM_K4 = (2560 + 256 * 65) * 4;
    const int SM_KOF = (21568 + 64 + 16) * 4;      // ~86.6 KB -> 2 CTA/SM

    cudaFuncSetAttribute(k_inproj,  cudaFuncAttributeMaxDynamicSharedMemorySize, SM_K2);
    cudaFuncSetAttribute(k_xproj,   cudaFuncAttributeMaxDynamicSharedMemorySize, SM_K4);
    cudaFuncSetAttribute(k_outfin,  cudaFuncAttributeMaxDynamicSharedMemorySize, SM_KOF);

    k_combine<<<32, 256>>>(Wfp, Wip, bip, bfp);
    k_combine2<<<128, 256>>>(Win);
    k_inproj<<<dim3(TOK / 64, 4), 256, SM_K2>>>(x, wn1, cw, cb);
    k_xproj<<<TOK / 64, 256, SM_K4>>>(Xp, Wdt, bdt);
    k_scan<<<NCH, 256>>>(Alog, Dpar);
    k_outfin<<<TOK / 64, 256, SM_KOF>>>(Wmo, wn2, wn1, Wwp, bwp, Wop, bop, x, out);
}